// round 6
// baseline (speedup 1.0000x reference)
#include <cuda_runtime.h>
#include <math.h>
#include <stdint.h>

#define B_    32
#define NPTS  2048
#define S1_   512
#define K1_   48
#define S2_   128
#define K2_   64

// ---------------- scratch (__device__ globals; no allocations allowed) ----------------
__device__ float  g_xyz [B_*NPTS*3];
__device__ float  g_xyz1[B_*S1_*3];
__device__ float  g_xyz2[B_*S2_*3];
__device__ int    g_fi1 [B_*S1_];
__device__ int    g_fi2 [B_*S2_];
__device__ int    g_ni1 [B_*S1_*K1_];
__device__ int    g_ni2 [B_*S2_*K2_];
__device__ float  g_ya  [50331648];    // y1a (786432x64) / y2a (262144x128)
__device__ float  g_yb  [134217728];   // y1b (786432x128) / y2b (262144x512)
__device__ float  g_f1  [B_*S1_*128];
__device__ float  g_f2  [B_*S2_*512];
__device__ float  g_y3  [B_*S2_*512];
__device__ double g_psum[1048576];
__device__ double g_pssq[1048576];
__device__ float  g_scale[5*512];
__device__ float  g_bias [5*512];
__device__ float  g_wT  [354560];      // w1bT@0, w2aT@8192, w2bT@25344, w3T@90880

// ---------------- helpers ----------------
__global__ void k_transpose_pc(const float* __restrict__ pc) {
    int idx = blockIdx.x * blockDim.x + threadIdx.x;       // b*N + i
    if (idx >= B_*NPTS) return;
    int b = idx / NPTS, i = idx % NPTS;
    const float* p = pc + (size_t)b*3*NPTS + i;
    float x = p[0], y = p[NPTS], z = p[2*NPTS];
    float* o = g_xyz + (size_t)idx*3;
    o[0] = x; o[1] = y; o[2] = z;
}

__global__ void k_transpose_w(const float* __restrict__ W, float* __restrict__ WT,
                              int OC, int IC) {
    int idx = blockIdx.x * blockDim.x + threadIdx.x;
    if (idx >= OC*IC) return;
    int o = idx / IC, i = idx % IC;
    WT[i*OC + o] = W[idx];
}

// ---------------- FPS: one CTA per batch, 256 threads, NPT points per thread ----------
template<int NPT>
__global__ void k_fps(const float* __restrict__ xyz, int n, int npoint,
                      int* __restrict__ fidx, float* __restrict__ oxyz) {
    const int b = blockIdx.x, tid = threadIdx.x;
    const float* base = xyz + (size_t)b*n*3;
    float lx[NPT], ly[NPT], lz[NPT], ld[NPT];
#pragma unroll
    for (int j = 0; j < NPT; j++) {
        int i = tid + j*256;
        lx[j] = base[i*3]; ly[j] = base[i*3+1]; lz[j] = base[i*3+2];
        ld[j] = 1e10f;
    }
    __shared__ float spx, spy, spz;
    __shared__ float swv[8];
    __shared__ int   swi[8];
    if (tid == 0) { fidx[(size_t)b*npoint] = 0; spx = base[0]; spy = base[1]; spz = base[2]; }
    __syncthreads();
    for (int s = 1; s < npoint; s++) {
        float px = spx, py = spy, pz = spz;
        float bv = -1.0f; int bi = 0;
#pragma unroll
        for (int j = 0; j < NPT; j++) {
            float dx = lx[j]-px, dy = ly[j]-py, dz = lz[j]-pz;
            // match JAX: square then left-to-right sum, NO fma contraction
            float d = __fadd_rn(__fadd_rn(__fmul_rn(dx,dx), __fmul_rn(dy,dy)), __fmul_rn(dz,dz));
            float nd = fminf(ld[j], d); ld[j] = nd;
            int i = tid + j*256;
            if (nd > bv) { bv = nd; bi = i; }   // ascending i -> first-max kept
        }
#pragma unroll
        for (int off = 16; off; off >>= 1) {
            float ov = __shfl_down_sync(0xffffffffu, bv, off);
            int   oi = __shfl_down_sync(0xffffffffu, bi, off);
            if (ov > bv || (ov == bv && oi < bi)) { bv = ov; bi = oi; }
        }
        if ((tid & 31) == 0) { swv[tid>>5] = bv; swi[tid>>5] = bi; }
        __syncthreads();
        if (tid == 0) {
            float v = swv[0]; int ii = swi[0];
#pragma unroll
            for (int w = 1; w < 8; w++)
                if (swv[w] > v || (swv[w] == v && swi[w] < ii)) { v = swv[w]; ii = swi[w]; }
            fidx[(size_t)b*npoint + s] = ii;
            spx = base[ii*3]; spy = base[ii*3+1]; spz = base[ii*3+2];
        }
        __syncthreads();
    }
    for (int s = tid; s < npoint; s += 256) {
        int ii = fidx[(size_t)b*npoint + s];
        oxyz[((size_t)b*npoint + s)*3 + 0] = base[ii*3];
        oxyz[((size_t)b*npoint + s)*3 + 1] = base[ii*3+1];
        oxyz[((size_t)b*npoint + s)*3 + 2] = base[ii*3+2];
    }
}

// ---------------- ball query: warp per center, ordered ballot collection ------------
__global__ void k_ballquery(const float* __restrict__ xyz, const float* __restrict__ ctr,
                            int* __restrict__ ni, int n, int S, int ns, float r2, int nwarps) {
    int gw = (blockIdx.x * blockDim.x + threadIdx.x) >> 5;
    int lane = threadIdx.x & 31;
    if (gw >= nwarps) return;
    int b = gw / S, c = gw % S;
    const float* cp = ctr + ((size_t)b*S + c)*3;
    float cx = cp[0], cy = cp[1], cz = cp[2];
    const float* pb = xyz + (size_t)b*n*3;
    int* out = ni + (size_t)gw*ns;
    int cnt = 0, first = 0; bool havefirst = false;
    for (int base = 0; base < n; base += 32) {
        int i = base + lane;
        bool inr = false;
        if (i < n) {
            float dx = cx - pb[i*3], dy = cy - pb[i*3+1], dz = cz - pb[i*3+2];
            float d2 = __fadd_rn(__fadd_rn(__fmul_rn(dx,dx), __fmul_rn(dy,dy)), __fmul_rn(dz,dz));
            inr = d2 < r2;
        }
        unsigned m = __ballot_sync(0xffffffffu, inr);
        if (!havefirst && m) { first = base + __ffs(m) - 1; havefirst = true; }
        int pos = cnt + __popc(m & ((1u << lane) - 1u));
        if (inr && pos < ns) out[pos] = i;
        cnt += __popc(m);
        if (cnt >= ns) break;
    }
    if (cnt > ns) cnt = ns;
    if (!havefirst) first = 0;
    for (int j = cnt + lane; j < ns; j += 32) out[j] = first;
}

// ---------------- layer 1a: 6->64, fused stats -------------------------------------
// grid 3072 x 256 (64 oc-threads x 4 points); 64 iters -> 256 pts/block
__global__ void k_layer1a(const float* __restrict__ w1a) {
    int tid = threadIdx.x;
    int oc = tid & 63, pg = tid >> 6;
    float w0 = w1a[oc*6+0], w1 = w1a[oc*6+1], w2 = w1a[oc*6+2];
    float w3 = w1a[oc*6+3], w4 = w1a[oc*6+4], w5 = w1a[oc*6+5];
    double tsum = 0, tssq = 0;
    int p0 = blockIdx.x * 256;
    for (int it = 0; it < 64; it++) {
        int p = p0 + it*4 + pg;                    // (b*S1+s)*K1+k
        int bs = p / K1_;
        int b = bs >> 9;
        int nb = g_ni1[p];
        const float* gp = g_xyz  + ((size_t)b*NPTS + nb)*3;
        const float* cp = g_xyz1 + (size_t)bs*3;
        float gx = gp[0], gy = gp[1], gz = gp[2];
        float rx = gx - cp[0], ry = gy - cp[1], rz = gz - cp[2];
        float v = rx*w0 + ry*w1 + rz*w2 + gx*w3 + gy*w4 + gz*w5;
        g_ya[(size_t)p*64 + oc] = v;
        tsum += v; tssq += (double)v * (double)v;
    }
    __shared__ double sh[512];
    sh[tid] = tsum; sh[256+tid] = tssq;
    __syncthreads();
    if (pg == 0) {
#pragma unroll
        for (int g = 1; g < 4; g++) { tsum += sh[g*64+oc]; tssq += sh[256+g*64+oc]; }
        g_psum[blockIdx.x*64 + oc] = tsum;
        g_pssq[blockIdx.x*64 + oc] = tssq;
    }
}

// ---------------- finalize BN stats -> scale/bias ----------------------------------
__global__ void k_finalize(const double* __restrict__ ps, const double* __restrict__ pq,
                           int G, int C, double cnt,
                           const float* __restrict__ gamma, const float* __restrict__ beta,
                           float* __restrict__ sc, float* __restrict__ bs_) {
    int c = blockIdx.x;
    double s = 0, q = 0;
    for (int g = threadIdx.x; g < G; g += 256) { s += ps[(size_t)g*C + c]; q += pq[(size_t)g*C + c]; }
    __shared__ double sd[256], sq_[256];
    sd[threadIdx.x] = s; sq_[threadIdx.x] = q;
    __syncthreads();
    for (int off = 128; off; off >>= 1) {
        if (threadIdx.x < off) { sd[threadIdx.x] += sd[threadIdx.x+off]; sq_[threadIdx.x] += sq_[threadIdx.x+off]; }
        __syncthreads();
    }
    if (threadIdx.x == 0) {
        double m = sd[0] / cnt;
        double v = sq_[0] / cnt - m*m;
        double inv = 1.0 / sqrt(v + 1e-5);
        double a = (double)gamma[c] * inv;
        sc[c]  = (float)a;
        bs_[c] = (float)((double)beta[c] - m*a);
    }
}

// ---------------- layer 1b: 64->128, fused norm-relu on input + stats ---------------
// grid 3072 x 128; 64 iters x 4 pts
__global__ void k_layer1b() {
    int tid = threadIdx.x;
    __shared__ float sin_[4][64], sa[64], sb[64];
    if (tid < 64) { sa[tid] = g_scale[tid]; sb[tid] = g_bias[tid]; }
    const float* WT = g_wT;                       // [64][128]
    double tsum = 0, tssq = 0;
    int p0 = blockIdx.x * 256;
    for (int it = 0; it < 64; it++) {
        int p = p0 + it*4;
        __syncthreads();
#pragma unroll
        for (int l = tid; l < 256; l += 128) {
            int pp = l >> 6, ic = l & 63;
            float v = g_ya[(size_t)(p+pp)*64 + ic];
            sin_[pp][ic] = fmaxf(fmaf(v, sa[ic], sb[ic]), 0.f);
        }
        __syncthreads();
        float a0 = 0, a1 = 0, a2 = 0, a3 = 0;
#pragma unroll
        for (int j = 0; j < 64; j++) {
            float w = WT[j*128 + tid];
            a0 = fmaf(sin_[0][j], w, a0); a1 = fmaf(sin_[1][j], w, a1);
            a2 = fmaf(sin_[2][j], w, a2); a3 = fmaf(sin_[3][j], w, a3);
        }
        g_yb[(size_t)(p+0)*128 + tid] = a0;
        g_yb[(size_t)(p+1)*128 + tid] = a1;
        g_yb[(size_t)(p+2)*128 + tid] = a2;
        g_yb[(size_t)(p+3)*128 + tid] = a3;
        tsum += (double)a0 + (double)a1 + (double)a2 + (double)a3;
        tssq += (double)a0*a0 + (double)a1*a1 + (double)a2*a2 + (double)a3*a3;
    }
    g_psum[blockIdx.x*128 + tid] = tsum;
    g_pssq[blockIdx.x*128 + tid] = tssq;
}

// ---------------- maxpool over K1 with fused norm-relu -----------------------------
__global__ void k_maxpool1() {
    int idx = blockIdx.x * blockDim.x + threadIdx.x;
    if (idx >= B_*S1_*128) return;
    int c = idx & 127, bs = idx >> 7;
    float a = g_scale[512 + c], bb = g_bias[512 + c];
    const float* base = g_yb + (size_t)bs*K1_*128 + c;
    float m = 0.f;
#pragma unroll 8
    for (int k = 0; k < K1_; k++) {
        float v = fmaxf(fmaf(base[k*128], a, bb), 0.f);
        m = fmaxf(m, v);
    }
    g_f1[idx] = m;
}

// ---------------- layer 2a: 134->128 (rel,gx,gathered f1), fused stats --------------
// grid 2048 x 128; 64 iters x 2 pts
__global__ void k_layer2a() {
    int tid = threadIdx.x;
    __shared__ float sin_[2][134];
    const float* WT = g_wT + 8192;                // [134][128]
    double tsum = 0, tssq = 0;
    int p0 = blockIdx.x * 128;
    for (int it = 0; it < 64; it++) {
        int p = p0 + it*2;
        __syncthreads();
#pragma unroll
        for (int pp = 0; pp < 2; pp++) {
            int P_ = p + pp;
            int bs = P_ >> 6;                     // b*S2+s
            int b  = bs >> 7;
            int nb = g_ni2[P_];
            sin_[pp][6 + tid] = g_f1[(((size_t)b*S1_) + nb)*128 + tid];
            if (tid < 6) {
                const float* gp = g_xyz1 + (((size_t)b*S1_) + nb)*3;
                const float* cp = g_xyz2 + (size_t)bs*3;
                sin_[pp][tid] = (tid < 3) ? (gp[tid] - cp[tid]) : gp[tid-3];
            }
        }
        __syncthreads();
        float a0 = 0, a1 = 0;
#pragma unroll 2
        for (int j = 0; j < 134; j++) {
            float w = WT[j*128 + tid];
            a0 = fmaf(sin_[0][j], w, a0); a1 = fmaf(sin_[1][j], w, a1);
        }
        g_ya[(size_t)p*128 + tid]     = a0;
        g_ya[(size_t)(p+1)*128 + tid] = a1;
        tsum += (double)a0 + (double)a1;
        tssq += (double)a0*a0 + (double)a1*a1;
    }
    g_psum[blockIdx.x*128 + tid] = tsum;
    g_pssq[blockIdx.x*128 + tid] = tssq;
}

// ---------------- layer 2b: 128->512, fused norm-relu on input + stats --------------
// grid 2048 x 512; 64 iters x 2 pts
__global__ void k_layer2b() {
    int tid = threadIdx.x;
    __shared__ float sin_[2][128], sa[128], sb[128];
    if (tid < 128) { sa[tid] = g_scale[1024 + tid]; sb[tid] = g_bias[1024 + tid]; }
    const float* WT = g_wT + 25344;               // [128][512]
    double tsum = 0, tssq = 0;
    int p0 = blockIdx.x * 128;
    for (int it = 0; it < 64; it++) {
        int p = p0 + it*2;
        __syncthreads();
        if (tid < 256) {
            int pp = tid >> 7, ic = tid & 127;
            float v = g_ya[(size_t)(p+pp)*128 + ic];
            sin_[pp][ic] = fmaxf(fmaf(v, sa[ic], sb[ic]), 0.f);
        }
        __syncthreads();
        float a0 = 0, a1 = 0;
#pragma unroll 8
        for (int j = 0; j < 128; j++) {
            float w = WT[j*512 + tid];
            a0 = fmaf(sin_[0][j], w, a0); a1 = fmaf(sin_[1][j], w, a1);
        }
        g_yb[(size_t)p*512 + tid]     = a0;
        g_yb[(size_t)(p+1)*512 + tid] = a1;
        tsum += (double)a0 + (double)a1;
        tssq += (double)a0*a0 + (double)a1*a1;
    }
    g_psum[blockIdx.x*512 + tid] = tsum;
    g_pssq[blockIdx.x*512 + tid] = tssq;
}

// ---------------- maxpool over K2 with fused norm-relu -----------------------------
__global__ void k_maxpool2() {
    int idx = blockIdx.x * blockDim.x + threadIdx.x;
    if (idx >= B_*S2_*512) return;
    int c = idx & 511, bs = idx >> 9;
    float a = g_scale[1536 + c], bb = g_bias[1536 + c];
    const float* base = g_yb + (size_t)bs*K2_*512 + c;
    float m = 0.f;
#pragma unroll 8
    for (int k = 0; k < K2_; k++) {
        float v = fmaxf(fmaf(base[k*512], a, bb), 0.f);
        m = fmaxf(m, v);
    }
    g_f2[idx] = m;
}

// ---------------- layer 3: 515->512, fused stats -----------------------------------
// grid 512 x 512; 8 pts/block
__global__ void k_layer3() {
    int tid = threadIdx.x;
    __shared__ float sin_[515];
    const float* WT = g_wT + 90880;               // [515][512]
    double tsum = 0, tssq = 0;
    int p0 = blockIdx.x * 8;
    for (int it = 0; it < 8; it++) {
        int p = p0 + it;                           // b*S2+s
        __syncthreads();
        sin_[3 + tid] = g_f2[(size_t)p*512 + tid];
        if (tid < 3) sin_[tid] = g_xyz2[(size_t)p*3 + tid];
        __syncthreads();
        float a = 0;
#pragma unroll 5
        for (int j = 0; j < 515; j++) a = fmaf(sin_[j], WT[j*512 + tid], a);
        g_y3[(size_t)p*512 + tid] = a;
        tsum += (double)a; tssq += (double)a*a;
    }
    g_psum[blockIdx.x*512 + tid] = tsum;
    g_pssq[blockIdx.x*512 + tid] = tssq;
}

// ---------------- final: norm-relu + max over 128 centroids ------------------------
__global__ void k_final(float* __restrict__ out) {
    int idx = blockIdx.x * blockDim.x + threadIdx.x;
    if (idx >= B_*512) return;
    int oc = idx & 511, b = idx >> 9;
    float a = g_scale[2048 + oc], bb = g_bias[2048 + oc];
    const float* base = g_y3 + (size_t)b*S2_*512 + oc;
    float m = 0.f;
#pragma unroll 8
    for (int p = 0; p < S2_; p++) {
        float v = fmaxf(fmaf(base[p*512], a, bb), 0.f);
        m = fmaxf(m, v);
    }
    out[idx] = m;
}

// ---------------- host ----------------
extern "C" void kernel_launch(void* const* d_in, const int* in_sizes, int n_in,
                              void* d_out, int out_size) {
    const float* pc  = (const float*)d_in[0];
    const float* w1a = (const float*)d_in[1];
    const float* g1a = (const float*)d_in[2];
    const float* b1a = (const float*)d_in[3];
    const float* w1b = (const float*)d_in[4];
    const float* g1b = (const float*)d_in[5];
    const float* b1b = (const float*)d_in[6];
    const float* w2a = (const float*)d_in[7];
    const float* g2a = (const float*)d_in[8];
    const float* b2a = (const float*)d_in[9];
    const float* w2b = (const float*)d_in[10];
    const float* g2b = (const float*)d_in[11];
    const float* b2b = (const float*)d_in[12];
    const float* w3  = (const float*)d_in[13];
    const float* g3  = (const float*)d_in[14];
    const float* b3  = (const float*)d_in[15];
    float* out = (float*)d_out;

    float *xyz, *xyz1, *xyz2, *wT, *scale, *bias;
    int *fi1, *fi2, *ni1, *ni2;
    double *psum, *pssq;
    cudaGetSymbolAddress((void**)&xyz,   g_xyz);
    cudaGetSymbolAddress((void**)&xyz1,  g_xyz1);
    cudaGetSymbolAddress((void**)&xyz2,  g_xyz2);
    cudaGetSymbolAddress((void**)&fi1,   g_fi1);
    cudaGetSymbolAddress((void**)&fi2,   g_fi2);
    cudaGetSymbolAddress((void**)&ni1,   g_ni1);
    cudaGetSymbolAddress((void**)&ni2,   g_ni2);
    cudaGetSymbolAddress((void**)&psum,  g_psum);
    cudaGetSymbolAddress((void**)&pssq,  g_pssq);
    cudaGetSymbolAddress((void**)&scale, g_scale);
    cudaGetSymbolAddress((void**)&bias,  g_bias);
    cudaGetSymbolAddress((void**)&wT,    g_wT);

    k_transpose_pc<<<256, 256>>>(pc);
    k_transpose_w<<<(128*64 + 255)/256, 256>>>(w1b, wT + 0,     128, 64);
    k_transpose_w<<<(128*134 + 255)/256, 256>>>(w2a, wT + 8192,  128, 134);
    k_transpose_w<<<(512*128 + 255)/256, 256>>>(w2b, wT + 25344, 512, 128);
    k_transpose_w<<<(512*515 + 255)/256, 256>>>(w3,  wT + 90880, 512, 515);

    // stage 1
    k_fps<8><<<32, 256>>>(xyz, 2048, 512, fi1, xyz1);
    k_ballquery<<<(32*512)/8, 256>>>(xyz, xyz1, ni1, 2048, 512, 48,
                                     (float)(0.23*0.23), 32*512);
    k_layer1a<<<3072, 256>>>(w1a);
    k_finalize<<<64, 256>>>(psum, pssq, 3072, 64, (double)(32*512*48),
                            g1a, b1a, scale + 0, bias + 0);
    k_layer1b<<<3072, 128>>>();
    k_finalize<<<128, 256>>>(psum, pssq, 3072, 128, (double)(32*512*48),
                             g1b, b1b, scale + 512, bias + 512);
    k_maxpool1<<<8192, 256>>>();

    // stage 2
    k_fps<2><<<32, 256>>>(xyz1, 512, 128, fi2, xyz2);
    k_ballquery<<<(32*128)/8, 256>>>(xyz1, xyz2, ni2, 512, 128, 64,
                                     (float)(0.32*0.32), 32*128);
    k_layer2a<<<2048, 128>>>();
    k_finalize<<<128, 256>>>(psum, pssq, 2048, 128, (double)(32*128*64),
                             g2a, b2a, scale + 1024, bias + 1024);
    k_layer2b<<<2048, 512>>>();
    k_finalize<<<512, 256>>>(psum, pssq, 2048, 512, (double)(32*128*64),
                             g2b, b2b, scale + 1536, bias + 1536);
    k_maxpool2<<<8192, 256>>>();

    // stage 3
    k_layer3<<<512, 512>>>();
    k_finalize<<<512, 256>>>(psum, pssq, 512, 512, (double)(32*128),
                             g3, b3, scale + 2048, bias + 2048);
    k_final<<<64, 256>>>(out);
}

// round 7
// speedup vs baseline: 1.0009x; 1.0009x over previous
#include <cuda_runtime.h>
#include <math.h>
#include <stdint.h>

#define B_    32
#define NPTS  2048
#define S1_   512
#define K1_   48
#define S2_   128
#define K2_   64

// ---------------- scratch (__device__ globals; no allocations allowed) ----------------
__device__ float  g_xyz [B_*NPTS*3];
__device__ float  g_xyz1[B_*S1_*3];
__device__ float  g_xyz2[B_*S2_*3];
__device__ int    g_fi1 [B_*S1_];
__device__ int    g_fi2 [B_*S2_];
__device__ int    g_ni1 [B_*S1_*K1_];
__device__ int    g_ni2 [B_*S2_*K2_];
__device__ float  g_ya  [50331648];    // y1a (786432x64) / y2a (262144x128)
__device__ float  g_yb  [134217728];   // y1b (786432x128) / y2b (262144x512)
__device__ float  g_f1  [B_*S1_*128];
__device__ float  g_f2  [B_*S2_*512];
__device__ float  g_y3  [B_*S2_*512];
__device__ double g_psum[1048576];
__device__ double g_pssq[1048576];
__device__ float  g_scale[5*512];
__device__ float  g_bias [5*512];
__device__ float  g_wT  [354560];      // w1bT@0, w2aT@8192, w2bT@25344, w3T@90880

// ---------------- helpers ----------------
__global__ void k_transpose_pc(const float* __restrict__ pc) {
    int idx = blockIdx.x * blockDim.x + threadIdx.x;       // b*N + i
    if (idx >= B_*NPTS) return;
    int b = idx / NPTS, i = idx % NPTS;
    const float* p = pc + (size_t)b*3*NPTS + i;
    float x = p[0], y = p[NPTS], z = p[2*NPTS];
    float* o = g_xyz + (size_t)idx*3;
    o[0] = x; o[1] = y; o[2] = z;
}

__global__ void k_transpose_w(const float* __restrict__ W, float* __restrict__ WT,
                              int OC, int IC) {
    int idx = blockIdx.x * blockDim.x + threadIdx.x;
    if (idx >= OC*IC) return;
    int o = idx / IC, i = idx % IC;
    WT[i*OC + o] = W[idx];
}

// ---------------- FPS: one CTA per batch, 256 threads, NPT points per thread ----------
template<int NPT>
__global__ void k_fps(const float* __restrict__ xyz, int n, int npoint,
                      int* __restrict__ fidx, float* __restrict__ oxyz) {
    const int b = blockIdx.x, tid = threadIdx.x;
    const float* base = xyz + (size_t)b*n*3;
    float lx[NPT], ly[NPT], lz[NPT], ld[NPT];
#pragma unroll
    for (int j = 0; j < NPT; j++) {
        int i = tid + j*256;
        lx[j] = base[i*3]; ly[j] = base[i*3+1]; lz[j] = base[i*3+2];
        ld[j] = 1e10f;
    }
    __shared__ float spx, spy, spz;
    __shared__ float swv[8];
    __shared__ int   swi[8];
    if (tid == 0) { fidx[(size_t)b*npoint] = 0; spx = base[0]; spy = base[1]; spz = base[2]; }
    __syncthreads();
    for (int s = 1; s < npoint; s++) {
        float px = spx, py = spy, pz = spz;
        float bv = -1.0f; int bi = 0;
#pragma unroll
        for (int j = 0; j < NPT; j++) {
            float dx = lx[j]-px, dy = ly[j]-py, dz = lz[j]-pz;
            // match JAX: square then left-to-right sum, NO fma contraction
            float d = __fadd_rn(__fadd_rn(__fmul_rn(dx,dx), __fmul_rn(dy,dy)), __fmul_rn(dz,dz));
            float nd = fminf(ld[j], d); ld[j] = nd;
            int i = tid + j*256;
            if (nd > bv) { bv = nd; bi = i; }   // ascending i -> first-max kept
        }
#pragma unroll
        for (int off = 16; off; off >>= 1) {
            float ov = __shfl_down_sync(0xffffffffu, bv, off);
            int   oi = __shfl_down_sync(0xffffffffu, bi, off);
            if (ov > bv || (ov == bv && oi < bi)) { bv = ov; bi = oi; }
        }
        if ((tid & 31) == 0) { swv[tid>>5] = bv; swi[tid>>5] = bi; }
        __syncthreads();
        if (tid == 0) {
            float v = swv[0]; int ii = swi[0];
#pragma unroll
            for (int w = 1; w < 8; w++)
                if (swv[w] > v || (swv[w] == v && swi[w] < ii)) { v = swv[w]; ii = swi[w]; }
            fidx[(size_t)b*npoint + s] = ii;
            spx = base[ii*3]; spy = base[ii*3+1]; spz = base[ii*3+2];
        }
        __syncthreads();
    }
    for (int s = tid; s < npoint; s += 256) {
        int ii = fidx[(size_t)b*npoint + s];
        oxyz[((size_t)b*npoint + s)*3 + 0] = base[ii*3];
        oxyz[((size_t)b*npoint + s)*3 + 1] = base[ii*3+1];
        oxyz[((size_t)b*npoint + s)*3 + 2] = base[ii*3+2];
    }
}

// ---------------- ball query: warp per center, ordered ballot collection ------------
__global__ void k_ballquery(const float* __restrict__ xyz, const float* __restrict__ ctr,
                            int* __restrict__ ni, int n, int S, int ns, float r2, int nwarps) {
    int gw = (blockIdx.x * blockDim.x + threadIdx.x) >> 5;
    int lane = threadIdx.x & 31;
    if (gw >= nwarps) return;
    int b = gw / S, c = gw % S;
    const float* cp = ctr + ((size_t)b*S + c)*3;
    float cx = cp[0], cy = cp[1], cz = cp[2];
    const float* pb = xyz + (size_t)b*n*3;
    int* out = ni + (size_t)gw*ns;
    int cnt = 0, first = 0; bool havefirst = false;
    for (int base = 0; base < n; base += 32) {
        int i = base + lane;
        bool inr = false;
        if (i < n) {
            float dx = cx - pb[i*3], dy = cy - pb[i*3+1], dz = cz - pb[i*3+2];
            float d2 = __fadd_rn(__fadd_rn(__fmul_rn(dx,dx), __fmul_rn(dy,dy)), __fmul_rn(dz,dz));
            inr = d2 < r2;
        }
        unsigned m = __ballot_sync(0xffffffffu, inr);
        if (!havefirst && m) { first = base + __ffs(m) - 1; havefirst = true; }
        int pos = cnt + __popc(m & ((1u << lane) - 1u));
        if (inr && pos < ns) out[pos] = i;
        cnt += __popc(m);
        if (cnt >= ns) break;
    }
    if (cnt > ns) cnt = ns;
    if (!havefirst) first = 0;
    for (int j = cnt + lane; j < ns; j += 32) out[j] = first;
}

// ---------------- layer 1a: 6->64, fused stats -------------------------------------
// grid 3072 x 256 (64 oc-threads x 4 points); 64 iters -> 256 pts/block
__global__ void k_layer1a(const float* __restrict__ w1a) {
    int tid = threadIdx.x;
    int oc = tid & 63, pg = tid >> 6;
    float w0 = w1a[oc*6+0], w1 = w1a[oc*6+1], w2 = w1a[oc*6+2];
    float w3 = w1a[oc*6+3], w4 = w1a[oc*6+4], w5 = w1a[oc*6+5];
    double tsum = 0, tssq = 0;
    int p0 = blockIdx.x * 256;
    for (int it = 0; it < 64; it++) {
        int p = p0 + it*4 + pg;                    // (b*S1+s)*K1+k
        int bs = p / K1_;
        int b = bs >> 9;
        int nb = g_ni1[p];
        const float* gp = g_xyz  + ((size_t)b*NPTS + nb)*3;
        const float* cp = g_xyz1 + (size_t)bs*3;
        float gx = gp[0], gy = gp[1], gz = gp[2];
        float rx = gx - cp[0], ry = gy - cp[1], rz = gz - cp[2];
        float v = rx*w0 + ry*w1 + rz*w2 + gx*w3 + gy*w4 + gz*w5;
        g_ya[(size_t)p*64 + oc] = v;
        tsum += v; tssq += (double)v * (double)v;
    }
    __shared__ double sh[512];
    sh[tid] = tsum; sh[256+tid] = tssq;
    __syncthreads();
    if (pg == 0) {
#pragma unroll
        for (int g = 1; g < 4; g++) { tsum += sh[g*64+oc]; tssq += sh[256+g*64+oc]; }
        g_psum[blockIdx.x*64 + oc] = tsum;
        g_pssq[blockIdx.x*64 + oc] = tssq;
    }
}

// ---------------- finalize BN stats -> scale/bias ----------------------------------
__global__ void k_finalize(const double* __restrict__ ps, const double* __restrict__ pq,
                           int G, int C, double cnt,
                           const float* __restrict__ gamma, const float* __restrict__ beta,
                           float* __restrict__ sc, float* __restrict__ bs_) {
    int c = blockIdx.x;
    double s = 0, q = 0;
    for (int g = threadIdx.x; g < G; g += 256) { s += ps[(size_t)g*C + c]; q += pq[(size_t)g*C + c]; }
    __shared__ double sd[256], sq_[256];
    sd[threadIdx.x] = s; sq_[threadIdx.x] = q;
    __syncthreads();
    for (int off = 128; off; off >>= 1) {
        if (threadIdx.x < off) { sd[threadIdx.x] += sd[threadIdx.x+off]; sq_[threadIdx.x] += sq_[threadIdx.x+off]; }
        __syncthreads();
    }
    if (threadIdx.x == 0) {
        double m = sd[0] / cnt;
        double v = sq_[0] / cnt - m*m;
        double inv = 1.0 / sqrt(v + 1e-5);
        double a = (double)gamma[c] * inv;
        sc[c]  = (float)a;
        bs_[c] = (float)((double)beta[c] - m*a);
    }
}

// ---------------- layer 1b: 64->128, fused norm-relu on input + stats ---------------
// grid 3072 x 128; 64 iters x 4 pts
__global__ void k_layer1b() {
    int tid = threadIdx.x;
    __shared__ float sin_[4][64], sa[64], sb[64];
    if (tid < 64) { sa[tid] = g_scale[tid]; sb[tid] = g_bias[tid]; }
    const float* WT = g_wT;                       // [64][128]
    double tsum = 0, tssq = 0;
    int p0 = blockIdx.x * 256;
    for (int it = 0; it < 64; it++) {
        int p = p0 + it*4;
        __syncthreads();
#pragma unroll
        for (int l = tid; l < 256; l += 128) {
            int pp = l >> 6, ic = l & 63;
            float v = g_ya[(size_t)(p+pp)*64 + ic];
            sin_[pp][ic] = fmaxf(fmaf(v, sa[ic], sb[ic]), 0.f);
        }
        __syncthreads();
        float a0 = 0, a1 = 0, a2 = 0, a3 = 0;
#pragma unroll
        for (int j = 0; j < 64; j++) {
            float w = WT[j*128 + tid];
            a0 = fmaf(sin_[0][j], w, a0); a1 = fmaf(sin_[1][j], w, a1);
            a2 = fmaf(sin_[2][j], w, a2); a3 = fmaf(sin_[3][j], w, a3);
        }
        g_yb[(size_t)(p+0)*128 + tid] = a0;
        g_yb[(size_t)(p+1)*128 + tid] = a1;
        g_yb[(size_t)(p+2)*128 + tid] = a2;
        g_yb[(size_t)(p+3)*128 + tid] = a3;
        tsum += (double)a0 + (double)a1 + (double)a2 + (double)a3;
        tssq += (double)a0*a0 + (double)a1*a1 + (double)a2*a2 + (double)a3*a3;
    }
    g_psum[blockIdx.x*128 + tid] = tsum;
    g_pssq[blockIdx.x*128 + tid] = tssq;
}

// ---------------- maxpool over K1 with fused norm-relu -----------------------------
__global__ void k_maxpool1() {
    int idx = blockIdx.x * blockDim.x + threadIdx.x;
    if (idx >= B_*S1_*128) return;
    int c = idx & 127, bs = idx >> 7;
    float a = g_scale[512 + c], bb = g_bias[512 + c];
    const float* base = g_yb + (size_t)bs*K1_*128 + c;
    float m = 0.f;
#pragma unroll 8
    for (int k = 0; k < K1_; k++) {
        float v = fmaxf(fmaf(base[k*128], a, bb), 0.f);
        m = fmaxf(m, v);
    }
    g_f1[idx] = m;
}

// ---------------- layer 2a: 134->128 (rel,gx,gathered f1), fused stats --------------
// grid 2048 x 128; 64 iters x 2 pts
__global__ void k_layer2a() {
    int tid = threadIdx.x;
    __shared__ float sin_[2][134];
    const float* WT = g_wT + 8192;                // [134][128]
    double tsum = 0, tssq = 0;
    int p0 = blockIdx.x * 128;
    for (int it = 0; it < 64; it++) {
        int p = p0 + it*2;
        __syncthreads();
#pragma unroll
        for (int pp = 0; pp < 2; pp++) {
            int P_ = p + pp;
            int bs = P_ >> 6;                     // b*S2+s
            int b  = bs >> 7;
            int nb = g_ni2[P_];
            sin_[pp][6 + tid] = g_f1[(((size_t)b*S1_) + nb)*128 + tid];
            if (tid < 6) {
                const float* gp = g_xyz1 + (((size_t)b*S1_) + nb)*3;
                const float* cp = g_xyz2 + (size_t)bs*3;
                sin_[pp][tid] = (tid < 3) ? (gp[tid] - cp[tid]) : gp[tid-3];
            }
        }
        __syncthreads();
        float a0 = 0, a1 = 0;
#pragma unroll 2
        for (int j = 0; j < 134; j++) {
            float w = WT[j*128 + tid];
            a0 = fmaf(sin_[0][j], w, a0); a1 = fmaf(sin_[1][j], w, a1);
        }
        g_ya[(size_t)p*128 + tid]     = a0;
        g_ya[(size_t)(p+1)*128 + tid] = a1;
        tsum += (double)a0 + (double)a1;
        tssq += (double)a0*a0 + (double)a1*a1;
    }
    g_psum[blockIdx.x*128 + tid] = tsum;
    g_pssq[blockIdx.x*128 + tid] = tssq;
}

// ---------------- layer 2b: 128->512, fused norm-relu on input + stats --------------
// grid 2048 x 512; 64 iters x 2 pts
__global__ void k_layer2b() {
    int tid = threadIdx.x;
    __shared__ float sin_[2][128], sa[128], sb[128];
    if (tid < 128) { sa[tid] = g_scale[1024 + tid]; sb[tid] = g_bias[1024 + tid]; }
    const float* WT = g_wT + 25344;               // [128][512]
    double tsum = 0, tssq = 0;
    int p0 = blockIdx.x * 128;
    for (int it = 0; it < 64; it++) {
        int p = p0 + it*2;
        __syncthreads();
        if (tid < 256) {
            int pp = tid >> 7, ic = tid & 127;
            float v = g_ya[(size_t)(p+pp)*128 + ic];
            sin_[pp][ic] = fmaxf(fmaf(v, sa[ic], sb[ic]), 0.f);
        }
        __syncthreads();
        float a0 = 0, a1 = 0;
#pragma unroll 8
        for (int j = 0; j < 128; j++) {
            float w = WT[j*512 + tid];
            a0 = fmaf(sin_[0][j], w, a0); a1 = fmaf(sin_[1][j], w, a1);
        }
        g_yb[(size_t)p*512 + tid]     = a0;
        g_yb[(size_t)(p+1)*512 + tid] = a1;
        tsum += (double)a0 + (double)a1;
        tssq += (double)a0*a0 + (double)a1*a1;
    }
    g_psum[blockIdx.x*512 + tid] = tsum;
    g_pssq[blockIdx.x*512 + tid] = tssq;
}

// ---------------- maxpool over K2 with fused norm-relu -----------------------------
__global__ void k_maxpool2() {
    int idx = blockIdx.x * blockDim.x + threadIdx.x;
    if (idx >= B_*S2_*512) return;
    int c = idx & 511, bs = idx >> 9;
    float a = g_scale[1536 + c], bb = g_bias[1536 + c];
    const float* base = g_yb + (size_t)bs*K2_*512 + c;
    float m = 0.f;
#pragma unroll 8
    for (int k = 0; k < K2_; k++) {
        float v = fmaxf(fmaf(base[k*512], a, bb), 0.f);
        m = fmaxf(m, v);
    }
    g_f2[idx] = m;
}

// ---------------- layer 3: 515->512, fused stats -----------------------------------
// grid 512 x 512; 8 pts/block
__global__ void k_layer3() {
    int tid = threadIdx.x;
    __shared__ float sin_[515];
    const float* WT = g_wT + 90880;               // [515][512]
    double tsum = 0, tssq = 0;
    int p0 = blockIdx.x * 8;
    for (int it = 0; it < 8; it++) {
        int p = p0 + it;                           // b*S2+s
        __syncthreads();
        sin_[3 + tid] = g_f2[(size_t)p*512 + tid];
        if (tid < 3) sin_[tid] = g_xyz2[(size_t)p*3 + tid];
        __syncthreads();
        float a = 0;
#pragma unroll 5
        for (int j = 0; j < 515; j++) a = fmaf(sin_[j], WT[j*512 + tid], a);
        g_y3[(size_t)p*512 + tid] = a;
        tsum += (double)a; tssq += (double)a*a;
    }
    g_psum[blockIdx.x*512 + tid] = tsum;
    g_pssq[blockIdx.x*512 + tid] = tssq;
}

// ---------------- final: norm-relu + max over 128 centroids ------------------------
__global__ void k_final(float* __restrict__ out) {
    int idx = blockIdx.x * blockDim.x + threadIdx.x;
    if (idx >= B_*512) return;
    int oc = idx & 511, b = idx >> 9;
    float a = g_scale[2048 + oc], bb = g_bias[2048 + oc];
    const float* base = g_y3 + (size_t)b*S2_*512 + oc;
    float m = 0.f;
#pragma unroll 8
    for (int p = 0; p < S2_; p++) {
        float v = fmaxf(fmaf(base[p*512], a, bb), 0.f);
        m = fmaxf(m, v);
    }
    out[idx] = m;
}

// ---------------- host ----------------
extern "C" void kernel_launch(void* const* d_in, const int* in_sizes, int n_in,
                              void* d_out, int out_size) {
    const float* pc  = (const float*)d_in[0];
    const float* w1a = (const float*)d_in[1];
    const float* g1a = (const float*)d_in[2];
    const float* b1a = (const float*)d_in[3];
    const float* w1b = (const float*)d_in[4];
    const float* g1b = (const float*)d_in[5];
    const float* b1b = (const float*)d_in[6];
    const float* w2a = (const float*)d_in[7];
    const float* g2a = (const float*)d_in[8];
    const float* b2a = (const float*)d_in[9];
    const float* w2b = (const float*)d_in[10];
    const float* g2b = (const float*)d_in[11];
    const float* b2b = (const float*)d_in[12];
    const float* w3  = (const float*)d_in[13];
    const float* g3  = (const float*)d_in[14];
    const float* b3  = (const float*)d_in[15];
    float* out = (float*)d_out;

    float *xyz, *xyz1, *xyz2, *wT, *scale, *bias;
    int *fi1, *fi2, *ni1, *ni2;
    double *psum, *pssq;
    cudaGetSymbolAddress((void**)&xyz,   g_xyz);
    cudaGetSymbolAddress((void**)&xyz1,  g_xyz1);
    cudaGetSymbolAddress((void**)&xyz2,  g_xyz2);
    cudaGetSymbolAddress((void**)&fi1,   g_fi1);
    cudaGetSymbolAddress((void**)&fi2,   g_fi2);
    cudaGetSymbolAddress((void**)&ni1,   g_ni1);
    cudaGetSymbolAddress((void**)&ni2,   g_ni2);
    cudaGetSymbolAddress((void**)&psum,  g_psum);
    cudaGetSymbolAddress((void**)&pssq,  g_pssq);
    cudaGetSymbolAddress((void**)&scale, g_scale);
    cudaGetSymbolAddress((void**)&bias,  g_bias);
    cudaGetSymbolAddress((void**)&wT,    g_wT);

    k_transpose_pc<<<256, 256>>>(pc);
    k_transpose_w<<<(128*64 + 255)/256, 256>>>(w1b, wT + 0,     128, 64);
    k_transpose_w<<<(128*134 + 255)/256, 256>>>(w2a, wT + 8192,  128, 134);
    k_transpose_w<<<(512*128 + 255)/256, 256>>>(w2b, wT + 25344, 512, 128);
    k_transpose_w<<<(512*515 + 255)/256, 256>>>(w3,  wT + 90880, 512, 515);

    // stage 1
    k_fps<8><<<32, 256>>>(xyz, 2048, 512, fi1, xyz1);
    k_ballquery<<<(32*512)/8, 256>>>(xyz, xyz1, ni1, 2048, 512, 48,
                                     (float)(0.23*0.23), 32*512);
    k_layer1a<<<3072, 256>>>(w1a);
    k_finalize<<<64, 256>>>(psum, pssq, 3072, 64, (double)(32*512*48),
                            g1a, b1a, scale + 0, bias + 0);
    k_layer1b<<<3072, 128>>>();
    k_finalize<<<128, 256>>>(psum, pssq, 3072, 128, (double)(32*512*48),
                             g1b, b1b, scale + 512, bias + 512);
    k_maxpool1<<<8192, 256>>>();

    // stage 2
    k_fps<2><<<32, 256>>>(xyz1, 512, 128, fi2, xyz2);
    k_ballquery<<<(32*128)/8, 256>>>(xyz1, xyz2, ni2, 512, 128, 64,
                                     (float)(0.32*0.32), 32*128);
    k_layer2a<<<2048, 128>>>();
    k_finalize<<<128, 256>>>(psum, pssq, 2048, 128, (double)(32*128*64),
                             g2a, b2a, scale + 1024, bias + 1024);
    k_layer2b<<<2048, 512>>>();
    k_finalize<<<512, 256>>>(psum, pssq, 2048, 512, (double)(32*128*64),
                             g2b, b2b, scale + 1536, bias + 1536);
    k_maxpool2<<<8192, 256>>>();

    // stage 3
    k_layer3<<<512, 512>>>();
    k_finalize<<<512, 256>>>(psum, pssq, 512, 512, (double)(32*128),
                             g3, b3, scale + 2048, bias + 2048);
    k_final<<<64, 256>>>(out);
}

// round 9
// speedup vs baseline: 1.2009x; 1.1998x over previous
#include <cuda_runtime.h>
#include <math.h>
#include <stdint.h>

#define B_    32
#define NPTS  2048
#define S1_   512
#define K1_   48
#define S2_   128
#define K2_   64

// ---------------- scratch (__device__ globals; no allocations allowed) ----------------
__device__ float  g_xyz [B_*NPTS*3];
__device__ float  g_xyz1[B_*S1_*3];
__device__ float  g_xyz2[B_*S2_*3];
__device__ int    g_fi1 [B_*S1_];
__device__ int    g_fi2 [B_*S2_];
__device__ int    g_ni1 [B_*S1_*K1_];
__device__ int    g_ni2 [B_*S2_*K2_];
__device__ float  g_ya  [50331648];    // y1a (786432x64) / y2a (262144x128)
__device__ float  g_yb  [134217728];   // y1b (786432x128) / y2b (262144x512)
__device__ float  g_f1  [B_*S1_*128];
__device__ float  g_f2  [B_*S2_*512];
__device__ float  g_y3  [B_*S2_*512];
__device__ double g_psum[16777216];
__device__ double g_pssq[16777216];
__device__ float  g_scale[5*512];
__device__ float  g_bias [5*512];
// w1bT@0 (64x128=8192), w2aT padded 144x128 @8192 (18432),
// w2bT 128x512 @26624 (65536), w3T padded 528x512 @92160 (270336)
__device__ float  g_wT  [393216];

// ---------------- helpers ----------------
__global__ void k_transpose_pc(const float* __restrict__ pc) {
    int idx = blockIdx.x * blockDim.x + threadIdx.x;
    if (idx >= B_*NPTS) return;
    int b = idx / NPTS, i = idx % NPTS;
    const float* p = pc + (size_t)b*3*NPTS + i;
    float x = p[0], y = p[NPTS], z = p[2*NPTS];
    float* o = g_xyz + (size_t)idx*3;
    o[0] = x; o[1] = y; o[2] = z;
}

__global__ void k_transpose_w(const float* __restrict__ W, float* __restrict__ WT,
                              int OC, int IC) {
    int idx = blockIdx.x * blockDim.x + threadIdx.x;
    if (idx >= OC*IC) return;
    int o = idx / IC, i = idx % IC;
    WT[i*OC + o] = W[idx];
}

__global__ void k_padw2a(const float* __restrict__ W) {   // -> 144x128, zero rows >=134
    int idx = blockIdx.x * blockDim.x + threadIdx.x;
    if (idx >= 144*128) return;
    int r = idx >> 7, oc = idx & 127;
    g_wT[8192 + idx] = (r < 134) ? W[oc*134 + r] : 0.f;
}
__global__ void k_padw3(const float* __restrict__ W) {    // -> 528x512, zero rows >=515
    int idx = blockIdx.x * blockDim.x + threadIdx.x;
    if (idx >= 528*512) return;
    int r = idx >> 9, oc = idx & 511;
    g_wT[92160 + idx] = (r < 515) ? W[oc*515 + r] : 0.f;
}

// ---------------- FPS (exact) ----------------
template<int NPT>
__global__ void k_fps(const float* __restrict__ xyz, int n, int npoint,
                      int* __restrict__ fidx, float* __restrict__ oxyz) {
    const int b = blockIdx.x, tid = threadIdx.x;
    const float* base = xyz + (size_t)b*n*3;
    float lx[NPT], ly[NPT], lz[NPT], ld[NPT];
#pragma unroll
    for (int j = 0; j < NPT; j++) {
        int i = tid + j*256;
        lx[j] = base[i*3]; ly[j] = base[i*3+1]; lz[j] = base[i*3+2];
        ld[j] = 1e10f;
    }
    __shared__ float spx, spy, spz;
    __shared__ float swv[8];
    __shared__ int   swi[8];
    if (tid == 0) { fidx[(size_t)b*npoint] = 0; spx = base[0]; spy = base[1]; spz = base[2]; }
    __syncthreads();
    for (int s = 1; s < npoint; s++) {
        float px = spx, py = spy, pz = spz;
        float bv = -1.0f; int bi = 0;
#pragma unroll
        for (int j = 0; j < NPT; j++) {
            float dx = lx[j]-px, dy = ly[j]-py, dz = lz[j]-pz;
            float d = __fadd_rn(__fadd_rn(__fmul_rn(dx,dx), __fmul_rn(dy,dy)), __fmul_rn(dz,dz));
            float nd = fminf(ld[j], d); ld[j] = nd;
            int i = tid + j*256;
            if (nd > bv) { bv = nd; bi = i; }
        }
#pragma unroll
        for (int off = 16; off; off >>= 1) {
            float ov = __shfl_down_sync(0xffffffffu, bv, off);
            int   oi = __shfl_down_sync(0xffffffffu, bi, off);
            if (ov > bv || (ov == bv && oi < bi)) { bv = ov; bi = oi; }
        }
        if ((tid & 31) == 0) { swv[tid>>5] = bv; swi[tid>>5] = bi; }
        __syncthreads();
        if (tid == 0) {
            float v = swv[0]; int ii = swi[0];
#pragma unroll
            for (int w = 1; w < 8; w++)
                if (swv[w] > v || (swv[w] == v && swi[w] < ii)) { v = swv[w]; ii = swi[w]; }
            fidx[(size_t)b*npoint + s] = ii;
            spx = base[ii*3]; spy = base[ii*3+1]; spz = base[ii*3+2];
        }
        __syncthreads();
    }
    for (int s = tid; s < npoint; s += 256) {
        int ii = fidx[(size_t)b*npoint + s];
        oxyz[((size_t)b*npoint + s)*3 + 0] = base[ii*3];
        oxyz[((size_t)b*npoint + s)*3 + 1] = base[ii*3+1];
        oxyz[((size_t)b*npoint + s)*3 + 2] = base[ii*3+2];
    }
}

// ---------------- ball query (exact) ----------------
__global__ void k_ballquery(const float* __restrict__ xyz, const float* __restrict__ ctr,
                            int* __restrict__ ni, int n, int S, int ns, float r2, int nwarps) {
    int gw = (blockIdx.x * blockDim.x + threadIdx.x) >> 5;
    int lane = threadIdx.x & 31;
    if (gw >= nwarps) return;
    int b = gw / S, c = gw % S;
    const float* cp = ctr + ((size_t)b*S + c)*3;
    float cx = cp[0], cy = cp[1], cz = cp[2];
    const float* pb = xyz + (size_t)b*n*3;
    int* out = ni + (size_t)gw*ns;
    int cnt = 0, first = 0; bool havefirst = false;
    for (int base = 0; base < n; base += 32) {
        int i = base + lane;
        bool inr = false;
        if (i < n) {
            float dx = cx - pb[i*3], dy = cy - pb[i*3+1], dz = cz - pb[i*3+2];
            float d2 = __fadd_rn(__fadd_rn(__fmul_rn(dx,dx), __fmul_rn(dy,dy)), __fmul_rn(dz,dz));
            inr = d2 < r2;
        }
        unsigned m = __ballot_sync(0xffffffffu, inr);
        if (!havefirst && m) { first = base + __ffs(m) - 1; havefirst = true; }
        int pos = cnt + __popc(m & ((1u << lane) - 1u));
        if (inr && pos < ns) out[pos] = i;
        cnt += __popc(m);
        if (cnt >= ns) break;
    }
    if (cnt > ns) cnt = ns;
    if (!havefirst) first = 0;
    for (int j = cnt + lane; j < ns; j += 32) out[j] = first;
}

// ---------------- layer 1a: 6->64, fused stats (unchanged) -------------------------
__global__ void k_layer1a(const float* __restrict__ w1a) {
    int tid = threadIdx.x;
    int oc = tid & 63, pg = tid >> 6;
    float w0 = w1a[oc*6+0], w1 = w1a[oc*6+1], w2 = w1a[oc*6+2];
    float w3 = w1a[oc*6+3], w4 = w1a[oc*6+4], w5 = w1a[oc*6+5];
    double tsum = 0, tssq = 0;
    int p0 = blockIdx.x * 256;
    for (int it = 0; it < 64; it++) {
        int p = p0 + it*4 + pg;
        int bs = p / K1_;
        int b = bs >> 9;
        int nb = g_ni1[p];
        const float* gp = g_xyz  + ((size_t)b*NPTS + nb)*3;
        const float* cp = g_xyz1 + (size_t)bs*3;
        float gx = gp[0], gy = gp[1], gz = gp[2];
        float rx = gx - cp[0], ry = gy - cp[1], rz = gz - cp[2];
        float v = rx*w0 + ry*w1 + rz*w2 + gx*w3 + gy*w4 + gz*w5;
        g_ya[(size_t)p*64 + oc] = v;
        tsum += v; tssq += (double)v * (double)v;
    }
    __shared__ double sh[512];
    sh[tid] = tsum; sh[256+tid] = tssq;
    __syncthreads();
    if (pg == 0) {
#pragma unroll
        for (int g = 1; g < 4; g++) { tsum += sh[g*64+oc]; tssq += sh[256+g*64+oc]; }
        g_psum[blockIdx.x*64 + oc] = tsum;
        g_pssq[blockIdx.x*64 + oc] = tssq;
    }
}

// ---------------- finalize BN stats -> scale/bias ----------------------------------
__global__ void k_finalize(const double* __restrict__ ps, const double* __restrict__ pq,
                           int G, int C, double cnt,
                           const float* __restrict__ gamma, const float* __restrict__ beta,
                           float* __restrict__ sc, float* __restrict__ bs_) {
    int c = blockIdx.x;
    double s = 0, q = 0;
    for (int g = threadIdx.x; g < G; g += 256) { s += ps[(size_t)g*C + c]; q += pq[(size_t)g*C + c]; }
    __shared__ double sd[256], sq_[256];
    sd[threadIdx.x] = s; sq_[threadIdx.x] = q;
    __syncthreads();
    for (int off = 128; off; off >>= 1) {
        if (threadIdx.x < off) { sd[threadIdx.x] += sd[threadIdx.x+off]; sq_[threadIdx.x] += sq_[threadIdx.x+off]; }
        __syncthreads();
    }
    if (threadIdx.x == 0) {
        double m = sd[0] / cnt;
        double v = sq_[0] / cnt - m*m;
        double inv = 1.0 / sqrt(v + 1e-5);
        double a = (double)gamma[c] * inv;
        sc[c]  = (float)a;
        bs_[c] = (float)((double)beta[c] - m*a);
    }
}

// ---------------- layer 1b tiled: 64->128, 64 pts/block, thread=4oc x 8pt ----------
__global__ void __launch_bounds__(256) k_layer1b_t() {
    __shared__ float sw[64*128];   // 32KB
    __shared__ float sh[64*36];
    int tid = threadIdx.x;
    int ocg = tid & 31, ptg = tid >> 5;
    for (int i = tid; i < 2048; i += 256)
        ((float4*)sw)[i] = ((const float4*)g_wT)[i];
    double dsum[4] = {0,0,0,0}, dssq[4] = {0,0,0,0};
    int p0 = blockIdx.x * 64;
    for (int tile = 0; tile < 2; tile++) {
        int pt0 = p0 + tile*32;
        __syncthreads();
        {
            int ic = tid & 63, ptq = tid >> 6;
            float a = g_scale[ic], bb = g_bias[ic];
#pragma unroll
            for (int k = 0; k < 8; k++) {
                int pt = ptq*8 + k;
                float v = g_ya[(size_t)(pt0+pt)*64 + ic];
                sh[ic*36 + pt] = fmaxf(fmaf(v, a, bb), 0.f);
            }
        }
        __syncthreads();
        float racc[4][4];
#pragma unroll
        for (int a = 0; a < 4; a++)
#pragma unroll
            for (int q = 0; q < 4; q++) racc[a][q] = 0.f;
#pragma unroll 4
        for (int j = 0; j < 64; j++) {
            float4 h = *(const float4*)&sh[j*36 + ptg*4];
            float4 w = *(const float4*)&sw[j*128 + ocg*4];
            float hq[4] = {h.x, h.y, h.z, h.w};
            float wa[4] = {w.x, w.y, w.z, w.w};
#pragma unroll
            for (int a = 0; a < 4; a++)
#pragma unroll
                for (int q = 0; q < 4; q++)
                    racc[a][q] = fmaf(hq[q], wa[a], racc[a][q]);
        }
#pragma unroll
        for (int q = 0; q < 4; q++) {
            int pt = pt0 + ptg*4 + q;
            float4 o; o.x = racc[0][q]; o.y = racc[1][q]; o.z = racc[2][q]; o.w = racc[3][q];
            *(float4*)&g_yb[(size_t)pt*128 + ocg*4] = o;
        }
#pragma unroll
        for (int a = 0; a < 4; a++)
#pragma unroll
            for (int q = 0; q < 4; q++) {
                double v = racc[a][q]; dsum[a] += v; dssq[a] += v*v;
            }
    }
    size_t row = (size_t)blockIdx.x*8 + ptg;
#pragma unroll
    for (int a = 0; a < 4; a++) {
        g_psum[row*128 + ocg*4 + a] = dsum[a];
        g_pssq[row*128 + ocg*4 + a] = dssq[a];
    }
}

// ---------------- maxpool1 -----------------------------
__global__ void k_maxpool1() {
    int idx = blockIdx.x * blockDim.x + threadIdx.x;
    if (idx >= B_*S1_*128) return;
    int c = idx & 127, bs = idx >> 7;
    float a = g_scale[512 + c], bb = g_bias[512 + c];
    const float* base = g_yb + (size_t)bs*K1_*128 + c;
    float m = 0.f;
#pragma unroll 8
    for (int k = 0; k < K1_; k++) {
        float v = fmaxf(fmaf(base[k*128], a, bb), 0.f);
        m = fmaxf(m, v);
    }
    g_f1[idx] = m;
}

// ---------------- layer 2a tiled: 134(pad144)->128, 32 pts/block, thread=4oc x 4pt --
__global__ void __launch_bounds__(256) k_layer2a_t() {
    __shared__ float sw[48*128];   // 24KB
    __shared__ float sh[48*36];
    __shared__ int   sni[32];
    __shared__ float scp[3];
    int tid = threadIdx.x;
    int ocg = tid & 31, ptg = tid >> 5;
    int p0 = blockIdx.x * 32;
    int bs = p0 >> 6, b = bs >> 7;
    if (tid < 32) sni[tid] = g_ni2[p0 + tid];
    if (tid < 3)  scp[tid] = g_xyz2[(size_t)bs*3 + tid];
    float racc[4][4];
#pragma unroll
    for (int a = 0; a < 4; a++)
#pragma unroll
        for (int q = 0; q < 4; q++) racc[a][q] = 0.f;
    for (int jc = 0; jc < 3; jc++) {
        __syncthreads();
        for (int i = tid; i < 1536; i += 256)
            ((float4*)sw)[i] = ((const float4*)(g_wT + 8192 + jc*48*128))[i];
        {
            int pt = tid >> 3, j0 = (tid & 7)*6;
            int nb = sni[pt];
            const float* f1p = g_f1  + ((size_t)b*S1_ + nb)*128;
            const float* gp  = g_xyz1 + ((size_t)b*S1_ + nb)*3;
#pragma unroll
            for (int k = 0; k < 6; k++) {
                int jj = j0 + k, ic = jc*48 + jj;
                float v;
                if (ic >= 134)     v = 0.f;
                else if (ic >= 6)  v = f1p[ic-6];
                else if (ic >= 3)  v = gp[ic-3];
                else               v = gp[ic] - scp[ic];
                sh[jj*36 + pt] = v;
            }
        }
        __syncthreads();
#pragma unroll 4
        for (int j = 0; j < 48; j++) {
            float4 h = *(const float4*)&sh[j*36 + ptg*4];
            float4 w = *(const float4*)&sw[j*128 + ocg*4];
            float hq[4] = {h.x, h.y, h.z, h.w};
            float wa[4] = {w.x, w.y, w.z, w.w};
#pragma unroll
            for (int a = 0; a < 4; a++)
#pragma unroll
                for (int q = 0; q < 4; q++)
                    racc[a][q] = fmaf(hq[q], wa[a], racc[a][q]);
        }
    }
    double dsum[4] = {0,0,0,0}, dssq[4] = {0,0,0,0};
#pragma unroll
    for (int q = 0; q < 4; q++) {
        int pt = p0 + ptg*4 + q;
        float4 o; o.x = racc[0][q]; o.y = racc[1][q]; o.z = racc[2][q]; o.w = racc[3][q];
        *(float4*)&g_ya[(size_t)pt*128 + ocg*4] = o;
#pragma unroll
        for (int a = 0; a < 4; a++) { double v = racc[a][q]; dsum[a] += v; dssq[a] += v*v; }
    }
    size_t row = (size_t)blockIdx.x*8 + ptg;
#pragma unroll
    for (int a = 0; a < 4; a++) {
        g_psum[row*128 + ocg*4 + a] = dsum[a];
        g_pssq[row*128 + ocg*4 + a] = dssq[a];
    }
}

// ---------------- layer 2b tiled: 128->512, 32 pts/block, 512 thr, thread=4oc x 8pt -
__global__ void __launch_bounds__(512) k_layer2b_t() {
    __shared__ float sw[16*512];   // 32KB
    __shared__ float sh[16*36];
    int tid = threadIdx.x;
    int ocg = tid & 127, ptg = tid >> 7;
    int p0 = blockIdx.x * 32;
    float racc[4][8];
#pragma unroll
    for (int a = 0; a < 4; a++)
#pragma unroll
        for (int q = 0; q < 8; q++) racc[a][q] = 0.f;
    for (int jc = 0; jc < 8; jc++) {
        __syncthreads();
        for (int i = tid; i < 2048; i += 512)
            ((float4*)sw)[i] = ((const float4*)(g_wT + 26624 + jc*16*512))[i];
        {
            int pt = tid >> 4, jj = tid & 15;
            int ic = jc*16 + jj;
            float v = g_ya[(size_t)(p0+pt)*128 + ic];
            sh[jj*36 + pt] = fmaxf(fmaf(v, g_scale[1024+ic], g_bias[1024+ic]), 0.f);
        }
        __syncthreads();
#pragma unroll
        for (int j = 0; j < 16; j++) {
            float4 w  = *(const float4*)&sw[j*512 + ocg*4];
            float4 h0 = *(const float4*)&sh[j*36 + ptg*4];
            float4 h1 = *(const float4*)&sh[j*36 + 16 + ptg*4];
            float wa[4] = {w.x, w.y, w.z, w.w};
            float hq[8] = {h0.x, h0.y, h0.z, h0.w, h1.x, h1.y, h1.z, h1.w};
#pragma unroll
            for (int a = 0; a < 4; a++)
#pragma unroll
                for (int q = 0; q < 8; q++)
                    racc[a][q] = fmaf(hq[q], wa[a], racc[a][q]);
        }
    }
    double dsum[4] = {0,0,0,0}, dssq[4] = {0,0,0,0};
#pragma unroll
    for (int t2 = 0; t2 < 2; t2++)
#pragma unroll
        for (int q = 0; q < 4; q++) {
            int pt = p0 + t2*16 + ptg*4 + q;
            int iq = t2*4 + q;
            float4 o; o.x = racc[0][iq]; o.y = racc[1][iq]; o.z = racc[2][iq]; o.w = racc[3][iq];
            *(float4*)&g_yb[(size_t)pt*512 + ocg*4] = o;
#pragma unroll
            for (int a = 0; a < 4; a++) { double v = racc[a][iq]; dsum[a] += v; dssq[a] += v*v; }
        }
    size_t row = (size_t)blockIdx.x*4 + ptg;
#pragma unroll
    for (int a = 0; a < 4; a++) {
        g_psum[row*512 + ocg*4 + a] = dsum[a];
        g_pssq[row*512 + ocg*4 + a] = dssq[a];
    }
}

// ---------------- maxpool2 -----------------------------
__global__ void k_maxpool2() {
    int idx = blockIdx.x * blockDim.x + threadIdx.x;
    if (idx >= B_*S2_*512) return;
    int c = idx & 511, bs = idx >> 9;
    float a = g_scale[1536 + c], bb = g_bias[1536 + c];
    const float* base = g_yb + (size_t)bs*K2_*512 + c;
    float m = 0.f;
#pragma unroll 8
    for (int k = 0; k < K2_; k++) {
        float v = fmaxf(fmaf(base[k*512], a, bb), 0.f);
        m = fmaxf(m, v);
    }
    g_f2[idx] = m;
}

// ---------------- layer 3 tiled: 515(pad528)->512, 16 pts/block, thread=8oc x 4pt ---
__global__ void __launch_bounds__(256) k_layer3_t() {
    __shared__ float sw[16*512];   // 32KB
    __shared__ float sh[16*20];
    int tid = threadIdx.x;
    int ocg = tid & 63, ptg = tid >> 6;
    int p0 = blockIdx.x * 16;
    float racc[8][4];
#pragma unroll
    for (int a = 0; a < 8; a++)
#pragma unroll
        for (int q = 0; q < 4; q++) racc[a][q] = 0.f;
    for (int jc = 0; jc < 33; jc++) {
        __syncthreads();
        for (int i = tid; i < 2048; i += 256)
            ((float4*)sw)[i] = ((const float4*)(g_wT + 92160 + jc*16*512))[i];
        {
            int pt = tid >> 4, jj = tid & 15;
            int ic = jc*16 + jj;
            float v;
            if (ic < 3)        v = g_xyz2[(size_t)(p0+pt)*3 + ic];
            else if (ic < 515) v = g_f2[(size_t)(p0+pt)*512 + ic - 3];
            else               v = 0.f;
            sh[jj*20 + pt] = v;
        }
        __syncthreads();
#pragma unroll
        for (int j = 0; j < 16; j++) {
            float4 h  = *(const float4*)&sh[j*20 + ptg*4];
            float4 w0 = *(const float4*)&sw[j*512 + ocg*8];
            float4 w1 = *(const float4*)&sw[j*512 + ocg*8 + 4];
            float hq[4] = {h.x, h.y, h.z, h.w};
            float wa[8] = {w0.x, w0.y, w0.z, w0.w, w1.x, w1.y, w1.z, w1.w};
#pragma unroll
            for (int a = 0; a < 8; a++)
#pragma unroll
                for (int q = 0; q < 4; q++)
                    racc[a][q] = fmaf(hq[q], wa[a], racc[a][q]);
        }
    }
    double dsum[8], dssq[8];
#pragma unroll
    for (int a = 0; a < 8; a++) { dsum[a] = 0; dssq[a] = 0; }
#pragma unroll
    for (int q = 0; q < 4; q++) {
        int pt = p0 + ptg*4 + q;
        float4 o0; o0.x = racc[0][q]; o0.y = racc[1][q]; o0.z = racc[2][q]; o0.w = racc[3][q];
        float4 o1; o1.x = racc[4][q]; o1.y = racc[5][q]; o1.z = racc[6][q]; o1.w = racc[7][q];
        *(float4*)&g_y3[(size_t)pt*512 + ocg*8]     = o0;
        *(float4*)&g_y3[(size_t)pt*512 + ocg*8 + 4] = o1;
#pragma unroll
        for (int a = 0; a < 8; a++) { double v = racc[a][q]; dsum[a] += v; dssq[a] += v*v; }
    }
    size_t row = (size_t)blockIdx.x*4 + ptg;
#pragma unroll
    for (int a = 0; a < 8; a++) {
        g_psum[row*512 + ocg*8 + a] = dsum[a];
        g_pssq[row*512 + ocg*8 + a] = dssq[a];
    }
}

// ---------------- final: norm-relu + max over 128 centroids ------------------------
__global__ void k_final(float* __restrict__ out) {
    int idx = blockIdx.x * blockDim.x + threadIdx.x;
    if (idx >= B_*512) return;
    int oc = idx & 511, b = idx >> 9;
    float a = g_scale[2048 + oc], bb = g_bias[2048 + oc];
    const float* base = g_y3 + (size_t)b*S2_*512 + oc;
    float m = 0.f;
#pragma unroll 8
    for (int p = 0; p < S2_; p++) {
        float v = fmaxf(fmaf(base[p*512], a, bb), 0.f);
        m = fmaxf(m, v);
    }
    out[idx] = m;
}

// ---------------- host ----------------
extern "C" void kernel_launch(void* const* d_in, const int* in_sizes, int n_in,
                              void* d_out, int out_size) {
    const float* pc  = (const float*)d_in[0];
    const float* w1a = (const float*)d_in[1];
    const float* g1a = (const float*)d_in[2];
    const float* b1a = (const float*)d_in[3];
    const float* w1b = (const float*)d_in[4];
    const float* g1b = (const float*)d_in[5];
    const float* b1b = (const float*)d_in[6];
    const float* w2a = (const float*)d_in[7];
    const float* g2a = (const float*)d_in[8];
    const float* b2a = (const float*)d_in[9];
    const float* w2b = (const float*)d_in[10];
    const float* g2b = (const float*)d_in[11];
    const float* b2b = (const float*)d_in[12];
    const float* w3  = (const float*)d_in[13];
    const float* g3  = (const float*)d_in[14];
    const float* b3  = (const float*)d_in[15];
    float* out = (float*)d_out;

    float *xyz, *xyz1, *xyz2, *wT, *scale, *bias;
    int *fi1, *fi2, *ni1, *ni2;
    double *psum, *pssq;
    cudaGetSymbolAddress((void**)&xyz,   g_xyz);
    cudaGetSymbolAddress((void**)&xyz1,  g_xyz1);
    cudaGetSymbolAddress((void**)&xyz2,  g_xyz2);
    cudaGetSymbolAddress((void**)&fi1,   g_fi1);
    cudaGetSymbolAddress((void**)&fi2,   g_fi2);
    cudaGetSymbolAddress((void**)&ni1,   g_ni1);
    cudaGetSymbolAddress((void**)&ni2,   g_ni2);
    cudaGetSymbolAddress((void**)&psum,  g_psum);
    cudaGetSymbolAddress((void**)&pssq,  g_pssq);
    cudaGetSymbolAddress((void**)&scale, g_scale);
    cudaGetSymbolAddress((void**)&bias,  g_bias);
    cudaGetSymbolAddress((void**)&wT,    g_wT);

    k_transpose_pc<<<256, 256>>>(pc);
    k_transpose_w<<<(128*64 + 255)/256, 256>>>(w1b, wT + 0, 128, 64);
    k_padw2a<<<(144*128 + 255)/256, 256>>>(w2a);
    k_transpose_w<<<(512*128 + 255)/256, 256>>>(w2b, wT + 26624, 512, 128);
    k_padw3<<<(528*512 + 255)/256, 256>>>(w3);

    // stage 1
    k_fps<8><<<32, 256>>>(xyz, 2048, 512, fi1, xyz1);
    k_ballquery<<<(32*512)/8, 256>>>(xyz, xyz1, ni1, 2048, 512, 48,
                                     (float)(0.23*0.23), 32*512);
    k_layer1a<<<3072, 256>>>(w1a);
    k_finalize<<<64, 256>>>(psum, pssq, 3072, 64, (double)(32*512*48),
                            g1a, b1a, scale + 0, bias + 0);
    k_layer1b_t<<<12288, 256>>>();
    k_finalize<<<128, 256>>>(psum, pssq, 98304, 128, (double)(32*512*48),
                             g1b, b1b, scale + 512, bias + 512);
    k_maxpool1<<<8192, 256>>>();

    // stage 2
    k_fps<2><<<32, 256>>>(xyz1, 512, 128, fi2, xyz2);
    k_ballquery<<<(32*128)/8, 256>>>(xyz1, xyz2, ni2, 512, 128, 64,
                                     (float)(0.32*0.32), 32*128);
    k_layer2a_t<<<8192, 256>>>();
    k_finalize<<<128, 256>>>(psum, pssq, 65536, 128, (double)(32*128*64),
                             g2a, b2a, scale + 1024, bias + 1024);
    k_layer2b_t<<<8192, 512>>>();
    k_finalize<<<512, 256>>>(psum, pssq, 32768, 512, (double)(32*128*64),
                             g2b, b2b, scale + 1536, bias + 1536);
    k_maxpool2<<<8192, 256>>>();

    // stage 3
    k_layer3_t<<<256, 256>>>();
    k_finalize<<<512, 256>>>(psum, pssq, 1024, 512, (double)(32*128),
                             g3, b3, scale + 2048, bias + 2048);
    k_final<<<64, 256>>>(out);
}

// round 10
// speedup vs baseline: 1.2716x; 1.0589x over previous
#include <cuda_runtime.h>
#include <math.h>
#include <stdint.h>

#define B_    32
#define NPTS  2048
#define S1_   512
#define K1_   48
#define S2_   128
#define K2_   64

typedef unsigned long long ull;

__device__ __forceinline__ ull fma2(ull a, ull b, ull c) {
    ull d; asm("fma.rn.f32x2 %0, %1, %2, %3;" : "=l"(d) : "l"(a), "l"(b), "l"(c)); return d;
}
__device__ __forceinline__ float lo32(ull v) { return __uint_as_float((unsigned)(v & 0xffffffffu)); }
__device__ __forceinline__ float hi32(ull v) { return __uint_as_float((unsigned)(v >> 32)); }
__device__ __forceinline__ ull dup32(float f) { unsigned u = __float_as_uint(f); return ((ull)u << 32) | (ull)u; }

// ---------------- scratch (__device__ globals; no allocations allowed) ----------------
__device__ float  g_xyz [B_*NPTS*3];
__device__ float  g_xyz1[B_*S1_*3];
__device__ float  g_xyz2[B_*S2_*3];
__device__ int    g_fi1 [B_*S1_];
__device__ int    g_fi2 [B_*S2_];
__device__ int    g_ni1 [B_*S1_*K1_];
__device__ int    g_ni2 [B_*S2_*K2_];
__device__ float  g_ya  [50331648];    // y1a (786432x64) / y2a (262144x128)
__device__ float  g_yb  [134217728];   // y1b (786432x128) / y2b (262144x512)
__device__ float  g_f1  [B_*S1_*128];
__device__ float  g_f2  [B_*S2_*512];
__device__ float  g_y3  [B_*S2_*512];
__device__ double g_psum[4194304];
__device__ double g_pssq[4194304];
__device__ float  g_scale[5*512];
__device__ float  g_bias [5*512];
// w1bT@0 (64x128=8192), w2aT padded 144x128 @8192 (18432),
// w2bT 128x512 @26624 (65536), w3T padded 528x512 @92160 (270336)
__device__ float  g_wT  [393216];

// ---------------- helpers ----------------
__global__ void k_transpose_pc(const float* __restrict__ pc) {
    int idx = blockIdx.x * blockDim.x + threadIdx.x;
    if (idx >= B_*NPTS) return;
    int b = idx / NPTS, i = idx % NPTS;
    const float* p = pc + (size_t)b*3*NPTS + i;
    float x = p[0], y = p[NPTS], z = p[2*NPTS];
    float* o = g_xyz + (size_t)idx*3;
    o[0] = x; o[1] = y; o[2] = z;
}

__global__ void k_transpose_w(const float* __restrict__ W, float* __restrict__ WT,
                              int OC, int IC) {
    int idx = blockIdx.x * blockDim.x + threadIdx.x;
    if (idx >= OC*IC) return;
    int o = idx / IC, i = idx % IC;
    WT[i*OC + o] = W[idx];
}

__global__ void k_padw2a(const float* __restrict__ W) {   // -> 144x128, zero rows >=134
    int idx = blockIdx.x * blockDim.x + threadIdx.x;
    if (idx >= 144*128) return;
    int r = idx >> 7, oc = idx & 127;
    g_wT[8192 + idx] = (r < 134) ? W[oc*134 + r] : 0.f;
}
__global__ void k_padw3(const float* __restrict__ W) {    // -> 528x512, zero rows >=515
    int idx = blockIdx.x * blockDim.x + threadIdx.x;
    if (idx >= 528*512) return;
    int r = idx >> 9, oc = idx & 511;
    g_wT[92160 + idx] = (r < 515) ? W[oc*515 + r] : 0.f;
}

// ---------------- FPS (exact) ----------------
template<int NPT>
__global__ void k_fps(const float* __restrict__ xyz, int n, int npoint,
                      int* __restrict__ fidx, float* __restrict__ oxyz) {
    const int b = blockIdx.x, tid = threadIdx.x;
    const float* base = xyz + (size_t)b*n*3;
    float lx[NPT], ly[NPT], lz[NPT], ld[NPT];
#pragma unroll
    for (int j = 0; j < NPT; j++) {
        int i = tid + j*256;
        lx[j] = base[i*3]; ly[j] = base[i*3+1]; lz[j] = base[i*3+2];
        ld[j] = 1e10f;
    }
    __shared__ float spx, spy, spz;
    __shared__ float swv[8];
    __shared__ int   swi[8];
    if (tid == 0) { fidx[(size_t)b*npoint] = 0; spx = base[0]; spy = base[1]; spz = base[2]; }
    __syncthreads();
    for (int s = 1; s < npoint; s++) {
        float px = spx, py = spy, pz = spz;
        float bv = -1.0f; int bi = 0;
#pragma unroll
        for (int j = 0; j < NPT; j++) {
            float dx = lx[j]-px, dy = ly[j]-py, dz = lz[j]-pz;
            float d = __fadd_rn(__fadd_rn(__fmul_rn(dx,dx), __fmul_rn(dy,dy)), __fmul_rn(dz,dz));
            float nd = fminf(ld[j], d); ld[j] = nd;
            int i = tid + j*256;
            if (nd > bv) { bv = nd; bi = i; }
        }
#pragma unroll
        for (int off = 16; off; off >>= 1) {
            float ov = __shfl_down_sync(0xffffffffu, bv, off);
            int   oi = __shfl_down_sync(0xffffffffu, bi, off);
            if (ov > bv || (ov == bv && oi < bi)) { bv = ov; bi = oi; }
        }
        if ((tid & 31) == 0) { swv[tid>>5] = bv; swi[tid>>5] = bi; }
        __syncthreads();
        if (tid == 0) {
            float v = swv[0]; int ii = swi[0];
#pragma unroll
            for (int w = 1; w < 8; w++)
                if (swv[w] > v || (swv[w] == v && swi[w] < ii)) { v = swv[w]; ii = swi[w]; }
            fidx[(size_t)b*npoint + s] = ii;
            spx = base[ii*3]; spy = base[ii*3+1]; spz = base[ii*3+2];
        }
        __syncthreads();
    }
    for (int s = tid; s < npoint; s += 256) {
        int ii = fidx[(size_t)b*npoint + s];
        oxyz[((size_t)b*npoint + s)*3 + 0] = base[ii*3];
        oxyz[((size_t)b*npoint + s)*3 + 1] = base[ii*3+1];
        oxyz[((size_t)b*npoint + s)*3 + 2] = base[ii*3+2];
    }
}

// ---------------- ball query (exact) ----------------
__global__ void k_ballquery(const float* __restrict__ xyz, const float* __restrict__ ctr,
                            int* __restrict__ ni, int n, int S, int ns, float r2, int nwarps) {
    int gw = (blockIdx.x * blockDim.x + threadIdx.x) >> 5;
    int lane = threadIdx.x & 31;
    if (gw >= nwarps) return;
    int b = gw / S, c = gw % S;
    const float* cp = ctr + ((size_t)b*S + c)*3;
    float cx = cp[0], cy = cp[1], cz = cp[2];
    const float* pb = xyz + (size_t)b*n*3;
    int* out = ni + (size_t)gw*ns;
    int cnt = 0, first = 0; bool havefirst = false;
    for (int base = 0; base < n; base += 32) {
        int i = base + lane;
        bool inr = false;
        if (i < n) {
            float dx = cx - pb[i*3], dy = cy - pb[i*3+1], dz = cz - pb[i*3+2];
            float d2 = __fadd_rn(__fadd_rn(__fmul_rn(dx,dx), __fmul_rn(dy,dy)), __fmul_rn(dz,dz));
            inr = d2 < r2;
        }
        unsigned m = __ballot_sync(0xffffffffu, inr);
        if (!havefirst && m) { first = base + __ffs(m) - 1; havefirst = true; }
        int pos = cnt + __popc(m & ((1u << lane) - 1u));
        if (inr && pos < ns) out[pos] = i;
        cnt += __popc(m);
        if (cnt >= ns) break;
    }
    if (cnt > ns) cnt = ns;
    if (!havefirst) first = 0;
    for (int j = cnt + lane; j < ns; j += 32) out[j] = first;
}

// ---------------- layer 1a: 6->64, fused stats -------------------------------------
__global__ void k_layer1a(const float* __restrict__ w1a) {
    int tid = threadIdx.x;
    int oc = tid & 63, pg = tid >> 6;
    float w0 = w1a[oc*6+0], w1 = w1a[oc*6+1], w2 = w1a[oc*6+2];
    float w3 = w1a[oc*6+3], w4 = w1a[oc*6+4], w5 = w1a[oc*6+5];
    double tsum = 0, tssq = 0;
    int p0 = blockIdx.x * 256;
    for (int it = 0; it < 64; it++) {
        int p = p0 + it*4 + pg;
        int bs = p / K1_;
        int b = bs >> 9;
        int nb = g_ni1[p];
        const float* gp = g_xyz  + ((size_t)b*NPTS + nb)*3;
        const float* cp = g_xyz1 + (size_t)bs*3;
        float gx = gp[0], gy = gp[1], gz = gp[2];
        float rx = gx - cp[0], ry = gy - cp[1], rz = gz - cp[2];
        float v = rx*w0 + ry*w1 + rz*w2 + gx*w3 + gy*w4 + gz*w5;
        g_ya[(size_t)p*64 + oc] = v;
        tsum += v; tssq += (double)v * (double)v;
    }
    __shared__ double sh[512];
    sh[tid] = tsum; sh[256+tid] = tssq;
    __syncthreads();
    if (pg == 0) {
#pragma unroll
        for (int g = 1; g < 4; g++) { tsum += sh[g*64+oc]; tssq += sh[256+g*64+oc]; }
        g_psum[blockIdx.x*64 + oc] = tsum;
        g_pssq[blockIdx.x*64 + oc] = tssq;
    }
}

// ---------------- finalize BN stats -> scale/bias ----------------------------------
__global__ void k_finalize(const double* __restrict__ ps, const double* __restrict__ pq,
                           int G, int C, double cnt,
                           const float* __restrict__ gamma, const float* __restrict__ beta,
                           float* __restrict__ sc, float* __restrict__ bs_) {
    int c = blockIdx.x;
    double s = 0, q = 0;
    for (int g = threadIdx.x; g < G; g += 256) { s += ps[(size_t)g*C + c]; q += pq[(size_t)g*C + c]; }
    __shared__ double sd[256], sq_[256];
    sd[threadIdx.x] = s; sq_[threadIdx.x] = q;
    __syncthreads();
    for (int off = 128; off; off >>= 1) {
        if (threadIdx.x < off) { sd[threadIdx.x] += sd[threadIdx.x+off]; sq_[threadIdx.x] += sq_[threadIdx.x+off]; }
        __syncthreads();
    }
    if (threadIdx.x == 0) {
        double m = sd[0] / cnt;
        double v = sq_[0] / cnt - m*m;
        double inv = 1.0 / sqrt(v + 1e-5);
        double a = (double)gamma[c] * inv;
        sc[c]  = (float)a;
        bs_[c] = (float)((double)beta[c] - m*a);
    }
}

// ---------------- layer 1b: 64->128, FFMA2, 64 pts/block, thread=4oc x 4pt x2tiles --
__global__ void __launch_bounds__(256) k_layer1b_t() {
    __shared__ float  sw[64*128];   // 32KB
    __shared__ float  shd[64*72];   // 18KB (h duplicated pairs, 32 pts -> 64 floats, pitch 72)
    __shared__ double sred[1024];   // 8KB
    int tid = threadIdx.x;
    int ocg = tid & 31, ptg = tid >> 5;
    for (int i = tid; i < 2048; i += 256)
        ((float4*)sw)[i] = ((const float4*)g_wT)[i];
    double dsum[4] = {0,0,0,0}, dssq[4] = {0,0,0,0};
    int p0 = blockIdx.x * 64;
    for (int tile = 0; tile < 2; tile++) {
        int pt0 = p0 + tile*32;
        __syncthreads();
        {
            int ic = tid & 63, ptq = tid >> 6;
            float a = g_scale[ic], bb = g_bias[ic];
            ull* row = (ull*)&shd[ic*72];
#pragma unroll
            for (int k = 0; k < 8; k++) {
                int pt = ptq*8 + k;
                float v = g_ya[(size_t)(pt0+pt)*64 + ic];
                row[pt] = dup32(fmaxf(fmaf(v, a, bb), 0.f));
            }
        }
        __syncthreads();
        ull accp[2][4];
#pragma unroll
        for (int pr = 0; pr < 2; pr++)
#pragma unroll
            for (int q = 0; q < 4; q++) accp[pr][q] = 0ull;
#pragma unroll 8
        for (int j = 0; j < 64; j++) {
            ulonglong2 wp = *(const ulonglong2*)&sw[j*128 + ocg*4];
            ulonglong2 h0 = *(const ulonglong2*)&shd[j*72 + ptg*8];
            ulonglong2 h1 = *(const ulonglong2*)&shd[j*72 + ptg*8 + 4];
            ull hh[4] = {h0.x, h0.y, h1.x, h1.y};
#pragma unroll
            for (int q = 0; q < 4; q++) {
                accp[0][q] = fma2(hh[q], wp.x, accp[0][q]);
                accp[1][q] = fma2(hh[q], wp.y, accp[1][q]);
            }
        }
#pragma unroll
        for (int q = 0; q < 4; q++) {
            int pt = pt0 + ptg*4 + q;
            float r0 = lo32(accp[0][q]), r1 = hi32(accp[0][q]);
            float r2 = lo32(accp[1][q]), r3 = hi32(accp[1][q]);
            float4 o; o.x = r0; o.y = r1; o.z = r2; o.w = r3;
            *(float4*)&g_yb[(size_t)pt*128 + ocg*4] = o;
            dsum[0] += r0; dssq[0] += (double)r0*r0;
            dsum[1] += r1; dssq[1] += (double)r1*r1;
            dsum[2] += r2; dssq[2] += (double)r2*r2;
            dsum[3] += r3; dssq[3] += (double)r3*r3;
        }
    }
    __syncthreads();
#pragma unroll
    for (int a = 0; a < 4; a++) sred[ptg*128 + ocg*4 + a] = dsum[a];
    __syncthreads();
    if (tid < 128) {
        double s = 0;
#pragma unroll
        for (int g = 0; g < 8; g++) s += sred[g*128 + tid];
        g_psum[(size_t)blockIdx.x*128 + tid] = s;
    }
    __syncthreads();
#pragma unroll
    for (int a = 0; a < 4; a++) sred[ptg*128 + ocg*4 + a] = dssq[a];
    __syncthreads();
    if (tid < 128) {
        double s = 0;
#pragma unroll
        for (int g = 0; g < 8; g++) s += sred[g*128 + tid];
        g_pssq[(size_t)blockIdx.x*128 + tid] = s;
    }
}

// ---------------- maxpool1 -----------------------------
__global__ void k_maxpool1() {
    int idx = blockIdx.x * blockDim.x + threadIdx.x;
    if (idx >= B_*S1_*128) return;
    int c = idx & 127, bs = idx >> 7;
    float a = g_scale[512 + c], bb = g_bias[512 + c];
    const float* base = g_yb + (size_t)bs*K1_*128 + c;
    float m = 0.f;
#pragma unroll 8
    for (int k = 0; k < K1_; k++) {
        float v = fmaxf(fmaf(base[k*128], a, bb), 0.f);
        m = fmaxf(m, v);
    }
    g_f1[idx] = m;
}

// ---------------- layer 2a: 134(pad144)->128, FFMA2, 32 pts/block, thread=4oc x 4pt -
__global__ void __launch_bounds__(256) k_layer2a_t() {
    __shared__ float  sw[48*128];   // 24KB
    __shared__ float  shd[48*72];   // 13.5KB
    __shared__ double sred[1024];   // 8KB
    __shared__ int    sni[32];
    __shared__ float  scp[3];
    int tid = threadIdx.x;
    int ocg = tid & 31, ptg = tid >> 5;
    int p0 = blockIdx.x * 32;
    int bs = p0 >> 6, b = bs >> 7;
    if (tid < 32) sni[tid] = g_ni2[p0 + tid];
    if (tid < 3)  scp[tid] = g_xyz2[(size_t)bs*3 + tid];
    ull accp[2][4];
#pragma unroll
    for (int pr = 0; pr < 2; pr++)
#pragma unroll
        for (int q = 0; q < 4; q++) accp[pr][q] = 0ull;
    for (int jc = 0; jc < 3; jc++) {
        __syncthreads();
        for (int i = tid; i < 1536; i += 256)
            ((float4*)sw)[i] = ((const float4*)(g_wT + 8192 + jc*48*128))[i];
        {
            int pt = tid >> 3, j0 = (tid & 7)*6;
            int nb = sni[pt];
            const float* f1p = g_f1  + ((size_t)b*S1_ + nb)*128;
            const float* gp  = g_xyz1 + ((size_t)b*S1_ + nb)*3;
#pragma unroll
            for (int k = 0; k < 6; k++) {
                int jj = j0 + k, ic = jc*48 + jj;
                float v;
                if (ic >= 134)     v = 0.f;
                else if (ic >= 6)  v = f1p[ic-6];
                else if (ic >= 3)  v = gp[ic-3];
                else               v = gp[ic] - scp[ic];
                ((ull*)&shd[jj*72])[pt] = dup32(v);
            }
        }
        __syncthreads();
#pragma unroll 4
        for (int j = 0; j < 48; j++) {
            ulonglong2 wp = *(const ulonglong2*)&sw[j*128 + ocg*4];
            ulonglong2 h0 = *(const ulonglong2*)&shd[j*72 + ptg*8];
            ulonglong2 h1 = *(const ulonglong2*)&shd[j*72 + ptg*8 + 4];
            ull hh[4] = {h0.x, h0.y, h1.x, h1.y};
#pragma unroll
            for (int q = 0; q < 4; q++) {
                accp[0][q] = fma2(hh[q], wp.x, accp[0][q]);
                accp[1][q] = fma2(hh[q], wp.y, accp[1][q]);
            }
        }
    }
    double dsum[4] = {0,0,0,0}, dssq[4] = {0,0,0,0};
#pragma unroll
    for (int q = 0; q < 4; q++) {
        int pt = p0 + ptg*4 + q;
        float r0 = lo32(accp[0][q]), r1 = hi32(accp[0][q]);
        float r2 = lo32(accp[1][q]), r3 = hi32(accp[1][q]);
        float4 o; o.x = r0; o.y = r1; o.z = r2; o.w = r3;
        *(float4*)&g_ya[(size_t)pt*128 + ocg*4] = o;
        dsum[0] += r0; dssq[0] += (double)r0*r0;
        dsum[1] += r1; dssq[1] += (double)r1*r1;
        dsum[2] += r2; dssq[2] += (double)r2*r2;
        dsum[3] += r3; dssq[3] += (double)r3*r3;
    }
    __syncthreads();
#pragma unroll
    for (int a = 0; a < 4; a++) sred[ptg*128 + ocg*4 + a] = dsum[a];
    __syncthreads();
    if (tid < 128) {
        double s = 0;
#pragma unroll
        for (int g = 0; g < 8; g++) s += sred[g*128 + tid];
        g_psum[(size_t)blockIdx.x*128 + tid] = s;
    }
    __syncthreads();
#pragma unroll
    for (int a = 0; a < 4; a++) sred[ptg*128 + ocg*4 + a] = dssq[a];
    __syncthreads();
    if (tid < 128) {
        double s = 0;
#pragma unroll
        for (int g = 0; g < 8; g++) s += sred[g*128 + tid];
        g_pssq[(size_t)blockIdx.x*128 + tid] = s;
    }
}

// ---------------- layer 2b: 128->512, FFMA2, 64 pts/block, 512 thr, thread=8oc x 8pt
__global__ void __launch_bounds__(512) k_layer2b_t() {
    __shared__ float  sw[16*512];   // 32KB
    __shared__ float  shd[16*128];  // 8KB (64 pts duplicated)
    __shared__ double sred[4096];   // 32KB
    int tid = threadIdx.x;
    int ocg = tid & 63, ptg = tid >> 6;
    int p0 = blockIdx.x * 64;
    ull accp[4][8];
#pragma unroll
    for (int pr = 0; pr < 4; pr++)
#pragma unroll
        for (int q = 0; q < 8; q++) accp[pr][q] = 0ull;
    for (int jc = 0; jc < 8; jc++) {
        __syncthreads();
        for (int i = tid; i < 2048; i += 512)
            ((float4*)sw)[i] = ((const float4*)(g_wT + 26624 + jc*16*512))[i];
        {
            int jj = tid & 15, ptb = tid >> 4;      // ptb 0..31
            int ic = jc*16 + jj;
            float a = g_scale[1024+ic], bb = g_bias[1024+ic];
            ull* row = (ull*)&shd[jj*128];
#pragma unroll
            for (int r = 0; r < 2; r++) {
                int pt = ptb + r*32;
                float v = g_ya[(size_t)(p0+pt)*128 + ic];
                row[pt] = dup32(fmaxf(fmaf(v, a, bb), 0.f));
            }
        }
        __syncthreads();
#pragma unroll
        for (int j = 0; j < 16; j++) {
            ulonglong2 w0 = *(const ulonglong2*)&sw[j*512 + ocg*8];
            ulonglong2 w1 = *(const ulonglong2*)&sw[j*512 + ocg*8 + 4];
            ulonglong2 h0 = *(const ulonglong2*)&shd[j*128 + ptg*16];
            ulonglong2 h1 = *(const ulonglong2*)&shd[j*128 + ptg*16 + 4];
            ulonglong2 h2 = *(const ulonglong2*)&shd[j*128 + ptg*16 + 8];
            ulonglong2 h3 = *(const ulonglong2*)&shd[j*128 + ptg*16 + 12];
            ull wa[4] = {w0.x, w0.y, w1.x, w1.y};
            ull hh[8] = {h0.x, h0.y, h1.x, h1.y, h2.x, h2.y, h3.x, h3.y};
#pragma unroll
            for (int a = 0; a < 4; a++)
#pragma unroll
                for (int q = 0; q < 8; q++)
                    accp[a][q] = fma2(hh[q], wa[a], accp[a][q]);
        }
    }
    double dsum[8], dssq[8];
#pragma unroll
    for (int a = 0; a < 8; a++) { dsum[a] = 0; dssq[a] = 0; }
#pragma unroll
    for (int q = 0; q < 8; q++) {
        int pt = p0 + ptg*8 + q;
        float r[8];
#pragma unroll
        for (int pr = 0; pr < 4; pr++) { r[2*pr] = lo32(accp[pr][q]); r[2*pr+1] = hi32(accp[pr][q]); }
        float4 o0; o0.x = r[0]; o0.y = r[1]; o0.z = r[2]; o0.w = r[3];
        float4 o1; o1.x = r[4]; o1.y = r[5]; o1.z = r[6]; o1.w = r[7];
        *(float4*)&g_yb[(size_t)pt*512 + ocg*8]     = o0;
        *(float4*)&g_yb[(size_t)pt*512 + ocg*8 + 4] = o1;
#pragma unroll
        for (int a = 0; a < 8; a++) { double v = r[a]; dsum[a] += v; dssq[a] += v*v; }
    }
    __syncthreads();
#pragma unroll
    for (int a = 0; a < 8; a++) sred[ptg*512 + ocg*8 + a] = dsum[a];
    __syncthreads();
    {
        double s = 0;
#pragma unroll
        for (int g = 0; g < 8; g++) s += sred[g*512 + tid];
        g_psum[(size_t)blockIdx.x*512 + tid] = s;
    }
    __syncthreads();
#pragma unroll
    for (int a = 0; a < 8; a++) sred[ptg*512 + ocg*8 + a] = dssq[a];
    __syncthreads();
    {
        double s = 0;
#pragma unroll
        for (int g = 0; g < 8; g++) s += sred[g*512 + tid];
        g_pssq[(size_t)blockIdx.x*512 + tid] = s;
    }
}

// ---------------- maxpool2 -----------------------------
__global__ void k_maxpool2() {
    int idx = blockIdx.x * blockDim.x + threadIdx.x;
    if (idx >= B_*S2_*512) return;
    int c = idx & 511, bs = idx >> 9;
    float a = g_scale[1536 + c], bb = g_bias[1536 + c];
    const float* base = g_yb + (size_t)bs*K2_*512 + c;
    float m = 0.f;
#pragma unroll 8
    for (int k = 0; k < K2_; k++) {
        float v = fmaxf(fmaf(base[k*512], a, bb), 0.f);
        m = fmaxf(m, v);
    }
    g_f2[idx] = m;
}

// ---------------- layer 3: 515(pad528)->512, FFMA2, 16 pts/block, thread=8oc x 4pt --
__global__ void __launch_bounds__(256) k_layer3_t() {
    __shared__ float sw[16*512];    // 32KB
    __shared__ float shd[16*40];    // 2.5KB (16 pts dup, pitch 40)
    int tid = threadIdx.x;
    int ocg = tid & 63, ptg = tid >> 6;
    int p0 = blockIdx.x * 16;
    ull accp[4][4];
#pragma unroll
    for (int pr = 0; pr < 4; pr++)
#pragma unroll
        for (int q = 0; q < 4; q++) accp[pr][q] = 0ull;
    for (int jc = 0; jc < 33; jc++) {
        __syncthreads();
        for (int i = tid; i < 2048; i += 256)
            ((float4*)sw)[i] = ((const float4*)(g_wT + 92160 + jc*16*512))[i];
        {
            int pt = tid >> 4, jj = tid & 15;
            int ic = jc*16 + jj;
            float v;
            if (ic < 3)        v = g_xyz2[(size_t)(p0+pt)*3 + ic];
            else if (ic < 515) v = g_f2[(size_t)(p0+pt)*512 + ic - 3];
            else               v = 0.f;
            ((ull*)&shd[jj*40])[pt] = dup32(v);
        }
        __syncthreads();
#pragma unroll
        for (int j = 0; j < 16; j++) {
            ulonglong2 w0 = *(const ulonglong2*)&sw[j*512 + ocg*8];
            ulonglong2 w1 = *(const ulonglong2*)&sw[j*512 + ocg*8 + 4];
            ulonglong2 h0 = *(const ulonglong2*)&shd[j*40 + ptg*8];
            ulonglong2 h1 = *(const ulonglong2*)&shd[j*40 + ptg*8 + 4];
            ull wa[4] = {w0.x, w0.y, w1.x, w1.y};
            ull hh[4] = {h0.x, h0.y, h1.x, h1.y};
#pragma unroll
            for (int a = 0; a < 4; a++)
#pragma unroll
                for (int q = 0; q < 4; q++)
                    accp[a][q] = fma2(hh[q], wa[a], accp[a][q]);
        }
    }
    double dsum[8], dssq[8];
#pragma unroll
    for (int a = 0; a < 8; a++) { dsum[a] = 0; dssq[a] = 0; }
#pragma unroll
    for (int q = 0; q < 4; q++) {
        int pt = p0 + ptg*4 + q;
        float r[8];
#pragma unroll
        for (int pr = 0; pr < 4; pr++) { r[2*pr] = lo32(accp[pr][q]); r[2*pr+1] = hi32(accp[pr][q]); }
        float4 o0; o0.x = r[0]; o0.y = r[1]; o0.z = r[2]; o0.w = r[3];
        float4 o1; o1.x = r[4]; o1.y = r[5]; o1.z = r[6]; o1.w = r[7];
        *(float4*)&g_y3[(size_t)pt*512 + ocg*8]     = o0;
        *(float4*)&g_y3[(size_t)pt*512 + ocg*8 + 4] = o1;
#pragma unroll
        for (int a = 0; a < 8; a++) { double v = r[a]; dsum[a] += v; dssq[a] += v*v; }
    }
    size_t row = (size_t)blockIdx.x*4 + ptg;
#pragma unroll
    for (int a = 0; a < 8; a++) {
        g_psum[row*512 + ocg*8 + a] = dsum[a];
        g_pssq[row*512 + ocg*8 + a] = dssq[a];
    }
}

// ---------------- final: norm-relu + max over 128 centroids ------------------------
__global__ void k_final(float* __restrict__ out) {
    int idx = blockIdx.x * blockDim.x + threadIdx.x;
    if (idx >= B_*512) return;
    int oc = idx & 511, b = idx >> 9;
    float a = g_scale[2048 + oc], bb = g_bias[2048 + oc];
    const float* base = g_y3 + (size_t)b*S2_*512 + oc;
    float m = 0.f;
#pragma unroll 8
    for (int p = 0; p < S2_; p++) {
        float v = fmaxf(fmaf(base[p*512], a, bb), 0.f);
        m = fmaxf(m, v);
    }
    out[idx] = m;
}

// ---------------- host ----------------
extern "C" void kernel_launch(void* const* d_in, const int* in_sizes, int n_in,
                              void* d_out, int out_size) {
    const float* pc  = (const float*)d_in[0];
    const float* w1a = (const float*)d_in[1];
    const float* g1a = (const float*)d_in[2];
    const float* b1a = (const float*)d_in[3];
    const float* w1b = (const float*)d_in[4];
    const float* g1b = (const float*)d_in[5];
    const float* b1b = (const float*)d_in[6];
    const float* w2a = (const float*)d_in[7];
    const float* g2a = (const float*)d_in[8];
    const float* b2a = (const float*)d_in[9];
    const float* w2b = (const float*)d_in[10];
    const float* g2b = (const float*)d_in[11];
    const float* b2b = (const float*)d_in[12];
    const float* w3  = (const float*)d_in[13];
    const float* g3  = (const float*)d_in[14];
    const float* b3  = (const float*)d_in[15];
    float* out = (float*)d_out;

    float *xyz, *xyz1, *xyz2, *wT, *scale, *bias;
    int *fi1, *fi2, *ni1, *ni2;
    double *psum, *pssq;
    cudaGetSymbolAddress((void**)&xyz,   g_xyz);
    cudaGetSymbolAddress((void**)&xyz1,  g_xyz1);
    cudaGetSymbolAddress((void**)&xyz2,  g_xyz2);
    cudaGetSymbolAddress((void**)&fi1,   g_fi1);
    cudaGetSymbolAddress((void**)&fi2,   g_fi2);
    cudaGetSymbolAddress((void**)&ni1,   g_ni1);
    cudaGetSymbolAddress((void**)&ni2,   g_ni2);
    cudaGetSymbolAddress((void**)&psum,  g_psum);
    cudaGetSymbolAddress((void**)&pssq,  g_pssq);
    cudaGetSymbolAddress((void**)&scale, g_scale);
    cudaGetSymbolAddress((void**)&bias,  g_bias);
    cudaGetSymbolAddress((void**)&wT,    g_wT);

    k_transpose_pc<<<256, 256>>>(pc);
    k_transpose_w<<<(128*64 + 255)/256, 256>>>(w1b, wT + 0, 128, 64);
    k_padw2a<<<(144*128 + 255)/256, 256>>>(w2a);
    k_transpose_w<<<(512*128 + 255)/256, 256>>>(w2b, wT + 26624, 512, 128);
    k_padw3<<<(528*512 + 255)/256, 256>>>(w3);

    // stage 1
    k_fps<8><<<32, 256>>>(xyz, 2048, 512, fi1, xyz1);
    k_ballquery<<<(32*512)/8, 256>>>(xyz, xyz1, ni1, 2048, 512, 48,
                                     (float)(0.23*0.23), 32*512);
    k_layer1a<<<3072, 256>>>(w1a);
    k_finalize<<<64, 256>>>(psum, pssq, 3072, 64, (double)(32*512*48),
                            g1a, b1a, scale + 0, bias + 0);
    k_layer1b_t<<<12288, 256>>>();
    k_finalize<<<128, 256>>>(psum, pssq, 12288, 128, (double)(32*512*48),
                             g1b, b1b, scale + 512, bias + 512);
    k_maxpool1<<<8192, 256>>>();

    // stage 2
    k_fps<2><<<32, 256>>>(xyz1, 512, 128, fi2, xyz2);
    k_ballquery<<<(32*128)/8, 256>>>(xyz1, xyz2, ni2, 512, 128, 64,
                                     (float)(0.32*0.32), 32*128);
    k_layer2a_t<<<8192, 256>>>();
    k_finalize<<<128, 256>>>(psum, pssq, 8192, 128, (double)(32*128*64),
                             g2a, b2a, scale + 1024, bias + 1024);
    k_layer2b_t<<<4096, 512>>>();
    k_finalize<<<512, 256>>>(psum, pssq, 4096, 512, (double)(32*128*64),
                             g2b, b2b, scale + 1536, bias + 1536);
    k_maxpool2<<<8192, 256>>>();

    // stage 3
    k_layer3_t<<<256, 256>>>();
    k_finalize<<<512, 256>>>(psum, pssq, 1024, 512, (double)(32*128),
                             g3, b3, scale + 2048, bias + 2048);
    k_final<<<64, 256>>>(out);
}